// round 13
// baseline (speedup 1.0000x reference)
#include <cuda_runtime.h>
#include <cuda_bf16.h>
#include <stdint.h>

#define BB 4
#define SS 2048
#define DM 1024
#define NH 16
#define DK 64
#define MTOT (BB*SS)   // 8192

// GEMM tiling (mma.sync path)
#define MT 128
#define NT 128
#define KT 32
#define NSLAB (DM/KT)          // 32
#define ROW_STRIDE 80
#define A_BYTES (MT*ROW_STRIDE)
#define STG_BYTES (4*A_BYTES)
#define GEMM_SMEM (2*STG_BYTES)

// Attention tiling
#define QROWS 128
#define KTILE 64
#define RS 144                              // smem row stride (64 bf16 + pad)
#define SM_QH 0
#define SM_QL (QROWS*RS)                    // 18432
#define KV_STG (4*KTILE*RS)                 // 36864 per stage
#define SM_ST(st) (2*QROWS*RS + (st)*KV_STG)
#define ATTN_SMEM (2*QROWS*RS + 2*KV_STG)   // 110592

// ---------------------------------------------------------------------------
// Scratch (static device globals -- no allocations anywhere)
__device__ float g_attn[MTOT*DM];
__device__ float g_y[MTOT*DM];
__device__ unsigned g_mbits[BB*SS*SS/32];
__device__ __nv_bfloat16 g_wt_hi[4][DM*DM];
__device__ __nv_bfloat16 g_wt_lo[4][DM*DM];
__device__ __nv_bfloat16 g_qh[BB*NH*SS*DK], g_ql[BB*NH*SS*DK];
__device__ __nv_bfloat16 g_kh[BB*NH*SS*DK], g_kl[BB*NH*SS*DK];
__device__ __nv_bfloat16 g_vh[BB*NH*SS*DK], g_vl[BB*NH*SS*DK];

// ---------------------------------------------------------------------------
// Helpers (base-target PTX only)
// ---------------------------------------------------------------------------
__device__ __forceinline__ uint32_t smem_u32(const void* p) {
    uint32_t a;
    asm("{ .reg .u64 t; cvta.to.shared.u64 t, %1; cvt.u32.u64 %0, t; }"
        : "=r"(a) : "l"(p));
    return a;
}
__device__ __forceinline__ void ldsm4(uint32_t* r, uint32_t addr) {
    asm volatile("ldmatrix.sync.aligned.m8n8.x4.shared.b16 {%0,%1,%2,%3}, [%4];"
                 : "=r"(r[0]), "=r"(r[1]), "=r"(r[2]), "=r"(r[3]) : "r"(addr));
}
__device__ __forceinline__ void ldsm4t(uint32_t* r, uint32_t addr) {
    asm volatile("ldmatrix.sync.aligned.m8n8.x4.trans.shared.b16 {%0,%1,%2,%3}, [%4];"
                 : "=r"(r[0]), "=r"(r[1]), "=r"(r[2]), "=r"(r[3]) : "r"(addr));
}
__device__ __forceinline__ void mma16816(float* d, const uint32_t* a, const uint32_t* b) {
    asm volatile(
        "mma.sync.aligned.m16n8k16.row.col.f32.bf16.bf16.f32 "
        "{%0,%1,%2,%3}, {%4,%5,%6,%7}, {%8,%9}, {%0,%1,%2,%3};"
        : "+f"(d[0]), "+f"(d[1]), "+f"(d[2]), "+f"(d[3])
        : "r"(a[0]), "r"(a[1]), "r"(a[2]), "r"(a[3]), "r"(b[0]), "r"(b[1]));
}
__device__ __forceinline__ void cp16(uint32_t saddr, const void* gptr) {
    asm volatile("cp.async.cg.shared.global [%0], [%1], 16;"
                 :: "r"(saddr), "l"(gptr) : "memory");
}
__device__ __forceinline__ void cp_commit() { asm volatile("cp.async.commit_group;" ::: "memory"); }
__device__ __forceinline__ void cp_wait0() { asm volatile("cp.async.wait_group 0;" ::: "memory"); }
__device__ __forceinline__ void cp_wait1() { asm volatile("cp.async.wait_group 1;" ::: "memory"); }

// fp32 pair -> bf16x2 hi + bf16x2 lo (x in low half)
__device__ __forceinline__ void split2(float x, float y, uint32_t& hi, uint32_t& lo) {
    __nv_bfloat162 h = __floats2bfloat162_rn(x, y);
    uint32_t hu = *reinterpret_cast<uint32_t*>(&h);
    float hx = __int_as_float(hu << 16);
    float hy = __int_as_float(hu & 0xffff0000u);
    __nv_bfloat162 l = __floats2bfloat162_rn(x - hx, y - hy);
    hi = hu; lo = *reinterpret_cast<uint32_t*>(&l);
}

// Fast exp on the FMA pipe (no MUFU). ~2e-6 rel err.
__device__ __forceinline__ float fexp(float x) {
    float y = fmaxf(x, -80.f) * 1.4426950408889634f;
    float t = y + 12582912.f;
    int   ni = __float_as_int(t) - 0x4B400000;
    float f = y - (t - 12582912.f);
    float p =            1.3333558146e-3f;
    p = fmaf(p, f, 9.6181291057e-3f);
    p = fmaf(p, f, 5.5504108664e-2f);
    p = fmaf(p, f, 2.4022650696e-1f);
    p = fmaf(p, f, 6.9314718056e-1f);
    p = fmaf(p, f, 1.0f);
    return __int_as_float(__float_as_int(p) + (ni << 23));
}

// ---------------------------------------------------------------------------
__global__ void pack_mask_kernel(const int* __restrict__ mask) {
    int i = blockIdx.x * blockDim.x + threadIdx.x;
    unsigned pred = (mask[i] != 0) ? 1u : 0u;
    unsigned w = __ballot_sync(0xffffffffu, pred);
    if ((threadIdx.x & 31) == 0) g_mbits[i >> 5] = w;
}

// ---------------------------------------------------------------------------
// Fused weight prep: grid (16,16,4); z selects which weight matrix.
// ---------------------------------------------------------------------------
__global__ __launch_bounds__(256) void prep_w_kernel(
    const float* __restrict__ W0, const float* __restrict__ W1,
    const float* __restrict__ W2, const float* __restrict__ W3)
{
    __shared__ float ts[64][65];
    int widx = blockIdx.z;
    const float* W = (widx == 0) ? W0 : (widx == 1) ? W1 : (widx == 2) ? W2 : W3;
    int k0 = blockIdx.x * 64, n0 = blockIdx.y * 64;
    int tid = threadIdx.x;
    #pragma unroll
    for (int i = 0; i < 16; i++) {
        int idx = tid + (i << 8);
        int r = idx >> 6, c = idx & 63;
        ts[c][r] = W[(size_t)(k0 + r) * DM + n0 + c];
    }
    __syncthreads();
    __nv_bfloat16* Hi = g_wt_hi[widx];
    __nv_bfloat16* Lo = g_wt_lo[widx];
    #pragma unroll
    for (int i = 0; i < 16; i++) {
        int idx = tid + (i << 8);
        int r = idx >> 6, c = idx & 63;
        float v = ts[r][c];
        __nv_bfloat16 h = __float2bfloat16_rn(v);
        __nv_bfloat16 l = __float2bfloat16_rn(v - __bfloat162float(h));
        size_t o = (size_t)(n0 + r) * DM + k0 + c;
        Hi[o] = h; Lo[o] = l;
    }
}

// ---------------------------------------------------------------------------
// bf16x3 GEMM (mma.sync). Fused projections (gridDim.z==3) / out-proj (mode 3).
// mma issue is TERM-MAJOR: per fi, 3 passes over fj (hi*hi, hi*lo, lo*hi) so
// consecutive mmas never share an accumulator (distance 4 >= HMMA latency).
// ---------------------------------------------------------------------------
__global__ __launch_bounds__(256, 2) void gemm_mma_kernel(
    const float* __restrict__ A0, const float* __restrict__ A1,
    const float* __restrict__ A2, int mode_in, const float* __restrict__ resid)
{
    extern __shared__ char smc[];
    const uint32_t sb = smem_u32(smc);
    const int tid = threadIdx.x, wid = tid >> 5, lane = tid & 31;
    const int bm = blockIdx.y * MT, bn = blockIdx.x * NT;
    const int warp_m = wid >> 2, warp_n = wid & 3;
    const int mode = (mode_in == 3) ? 3 : (int)blockIdx.z;
    const int widx = mode;
    const float* __restrict__ A =
        (mode == 3) ? (const float*)g_attn : (mode == 0) ? A0 : (mode == 1) ? A1 : A2;
    const __nv_bfloat16* __restrict__ BHi = g_wt_hi[widx];
    const __nv_bfloat16* __restrict__ BLo = g_wt_lo[widx];

    float acc[4][4][4];
    #pragma unroll
    for (int i = 0; i < 4; i++)
        #pragma unroll
        for (int j = 0; j < 4; j++)
            #pragma unroll
            for (int c = 0; c < 4; c++) acc[i][j][c] = 0.f;

    const int arow_ld = tid >> 1, acol_ld = (tid & 1) * 16;
    const int a_r = (lane & 15), a_c8 = (lane >> 4) * 8;
    const int b_n = (lane & 7) + ((lane & 16) ? 8 : 0);
    const int b_k8 = ((lane >> 3) & 1) * 8;

    auto issueB = [&](int s, int stage) {
        int k0 = s * KT;
        uint32_t bh = sb + stage * STG_BYTES + 2 * A_BYTES;
        uint32_t bl = bh + A_BYTES;
        #pragma unroll
        for (int i = 0; i < 2; i++) {
            int c = tid + (i << 8);
            int row = c >> 2, seg = c & 3;
            size_t go = (size_t)(bn + row) * DM + k0 + seg * 8;
            uint32_t so = (uint32_t)row * ROW_STRIDE + seg * 16;
            cp16(bh + so, BHi + go);
            cp16(bl + so, BLo + go);
        }
        cp_commit();
    };
    auto ldgA = [&](int s, float* af) {
        const float4* src = (const float4*)(A + (size_t)(bm + arow_ld) * DM + s * KT + acol_ld);
        #pragma unroll
        for (int q = 0; q < 4; q++) ((float4*)af)[q] = src[q];
    };
    auto stsA = [&](int stage, const float* af) {
        uint32_t ah = sb + stage * STG_BYTES;
        uint32_t al = ah + A_BYTES;
        uint32_t ro = (uint32_t)arow_ld * ROW_STRIDE + acol_ld * 2;
        #pragma unroll
        for (int q = 0; q < 4; q++) {
            uint32_t hv0, lv0, hv1, lv1;
            split2(af[4*q], af[4*q+1], hv0, lv0);
            split2(af[4*q+2], af[4*q+3], hv1, lv1);
            uint32_t so = ro + q * 8;
            asm volatile("st.shared.v2.b32 [%0], {%1,%2};" :: "r"(ah + so), "r"(hv0), "r"(hv1) : "memory");
            asm volatile("st.shared.v2.b32 [%0], {%1,%2};" :: "r"(al + so), "r"(lv0), "r"(lv1) : "memory");
        }
    };
    auto compute_half = [&](int stage, int ks) {
        uint32_t ah_b = sb + stage * STG_BYTES;
        uint32_t al_b = ah_b + A_BYTES;
        uint32_t bh_b = ah_b + 2 * A_BYTES;
        uint32_t bl_b = ah_b + 3 * A_BYTES;
        uint32_t bh[8], bl[8];
        #pragma unroll
        for (int p = 0; p < 2; p++) {
            uint32_t bo = (uint32_t)(warp_n * 32 + p * 16 + b_n) * ROW_STRIDE
                        + (ks * 16 + b_k8) * 2;
            ldsm4(bh + 4 * p, bh_b + bo);
            ldsm4(bl + 4 * p, bl_b + bo);
        }
        #pragma unroll
        for (int fi = 0; fi < 4; fi++) {
            uint32_t ao = (uint32_t)(warp_m * 64 + fi * 16 + a_r) * ROW_STRIDE
                        + (ks * 16 + a_c8) * 2;
            uint32_t ahf[4], alf[4];
            ldsm4(ahf, ah_b + ao);
            ldsm4(alf, al_b + ao);
            // term-major: 3 passes, each touching all 4 accumulators
            #pragma unroll
            for (int fj = 0; fj < 4; fj++)
                mma16816(acc[fi][fj], ahf, bh + (fj >> 1) * 4 + (fj & 1) * 2);
            #pragma unroll
            for (int fj = 0; fj < 4; fj++)
                mma16816(acc[fi][fj], ahf, bl + (fj >> 1) * 4 + (fj & 1) * 2);
            #pragma unroll
            for (int fj = 0; fj < 4; fj++)
                mma16816(acc[fi][fj], alf, bh + (fj >> 1) * 4 + (fj & 1) * 2);
        }
    };

    {
        float af[16];
        issueB(0, 0);
        ldgA(0, af);
        stsA(0, af);
        cp_wait0();
        __syncthreads();
    }
    for (int s = 0; s < NSLAB; s++) {
        int stage = s & 1;
        float af[16];
        bool pf = (s + 1 < NSLAB);
        if (pf) { issueB(s + 1, stage ^ 1); ldgA(s + 1, af); }
        compute_half(stage, 0);
        if (pf) stsA(stage ^ 1, af);
        compute_half(stage, 1);
        if (pf) cp_wait0();
        __syncthreads();
    }

    const int t4 = lane >> 2, tp = (lane & 3) * 2;
    #pragma unroll
    for (int fi = 0; fi < 4; fi++) {
        #pragma unroll
        for (int h2 = 0; h2 < 2; h2++) {
            int m = bm + warp_m * 64 + fi * 16 + t4 + h2 * 8;
            if (mode < 3) {
                __nv_bfloat16 *oh, *ol;
                if (mode == 0) { oh = g_qh; ol = g_ql; }
                else if (mode == 1) { oh = g_kh; ol = g_kl; }
                else { oh = g_vh; ol = g_vl; }
                float scale = (mode == 0) ? 0.125f : 1.0f;
                int b = m >> 11, srow = m & (SS - 1);
                #pragma unroll
                for (int fj = 0; fj < 4; fj++) {
                    int n = bn + warp_n * 32 + fj * 8 + tp;
                    int h = n >> 6, d = n & 63;
                    uint32_t hi, lo;
                    split2(acc[fi][fj][h2*2] * scale, acc[fi][fj][h2*2+1] * scale, hi, lo);
                    size_t o = ((((size_t)b * NH + h) * SS) + srow) * DK + d;
                    *(uint32_t*)(oh + o) = hi;
                    *(uint32_t*)(ol + o) = lo;
                }
            } else {
                #pragma unroll
                for (int fj = 0; fj < 4; fj++) {
                    int n = bn + warp_n * 32 + fj * 8 + tp;
                    size_t o = (size_t)m * DM + n;
                    float2 rv = *(const float2*)(resid + o);
                    *(float2*)(g_y + o) = make_float2(acc[fi][fj][h2*2] + rv.x,
                                                      acc[fi][fj][h2*2+1] + rv.y);
                }
            }
        }
    }
}

// ---------------------------------------------------------------------------
// Flash attention (bf16x3, mma.sync), fixed-shift softmax, term-major mma
// ordering (no back-to-back same-accumulator RAW), Q fragments hoisted out
// of the kt loop. 1 CTA/SM, regs unconstrained.
// ---------------------------------------------------------------------------
__global__ __launch_bounds__(256) void attn_mma_kernel() {
    extern __shared__ char smc[];
    const uint32_t sb = smem_u32(smc);
    const int tid = threadIdx.x, wp = tid >> 5, lane = tid & 31;
    const int qt = blockIdx.x & 15, h = (blockIdx.x >> 4) & 15, b = blockIdx.x >> 8;
    const size_t base = (size_t)(b * NH + h) * SS * DK;

    const __nv_bfloat16* qh_g = g_qh + base + (size_t)qt * QROWS * DK;
    const __nv_bfloat16* ql_g = g_ql + base + (size_t)qt * QROWS * DK;
    const __nv_bfloat16* kh_g = g_kh + base;
    const __nv_bfloat16* kl_g = g_kl + base;
    const __nv_bfloat16* vh_g = g_vh + base;
    const __nv_bfloat16* vl_g = g_vl + base;

    auto issue_tile = [&](int kt, int st) {
        uint32_t sbase = sb + SM_ST(st);
        #pragma unroll
        for (int i = 0; i < 8; i++) {
            int c = tid + (i << 8);
            int arr = i >> 1;
            int row = (c >> 3) & 63, seg = c & 7;
            const __nv_bfloat16* g =
                (arr == 0) ? kh_g : (arr == 1) ? kl_g : (arr == 2) ? vh_g : vl_g;
            cp16(sbase + arr * (KTILE*RS) + row * RS + seg * 16,
                 g + (size_t)(kt * KTILE + row) * DK + seg * 8);
        }
    };

    {
        #pragma unroll
        for (int i = 0; i < 8; i++) {
            int c = tid + (i << 8);
            int arr = i >> 2;
            int row = (c >> 3) & 127, seg = c & 7;
            const __nv_bfloat16* g = arr ? ql_g : qh_g;
            cp16(sb + (arr ? SM_QL : SM_QH) + row * RS + seg * 16,
                 g + (size_t)row * DK + seg * 8);
        }
        issue_tile(0, 0);
        cp_commit();
        issue_tile(1, 1);
        cp_commit();
    }

    float sacc[8][4], oacc[8][4];
    #pragma unroll
    for (int f = 0; f < 8; f++)
        #pragma unroll
        for (int c = 0; c < 4; c++) oacc[f][c] = 0.f;
    float l0 = 0.f, l1 = 0.f;

    const int t4 = lane >> 2, tp = lane & 3;
    const int r0g = qt * QROWS + wp * 16 + t4;
    const unsigned* mrow0 = g_mbits + ((size_t)b * SS + r0g) * (SS / 32);
    const unsigned* mrow1 = mrow0 + 8 * (SS / 32);

    // ---- hoist Q fragments (all 4 k-steps) out of the kt loop ----
    uint32_t qhf[4][4], qlf[4][4];
    cp_wait1();           // group(Q + tile0) complete
    __syncthreads();
    #pragma unroll
    for (int ks = 0; ks < 4; ks++) {
        uint32_t qoff = (uint32_t)(wp * 16 + (lane & 15)) * RS + ks * 32 + (lane >> 4) * 16;
        ldsm4(qhf[ks], sb + SM_QH + qoff);
        ldsm4(qlf[ks], sb + SM_QL + qoff);
    }

    for (int kt = 0; kt < 32; kt++) {
        int st = kt & 1;
        cp_wait1();
        __syncthreads();
        uint32_t KHb = sb + SM_ST(st);
        uint32_t KLb = KHb + KTILE*RS, VHb = KHb + 2*KTILE*RS, VLb = KHb + 3*KTILE*RS;

        // ---- S = Q K^T (bf16x3, term-major) ----
        #pragma unroll
        for (int f = 0; f < 8; f++)
            #pragma unroll
            for (int c = 0; c < 4; c++) sacc[f][c] = 0.f;
        #pragma unroll
        for (int ks = 0; ks < 4; ks++) {
            uint32_t khf[4][4], klf[4][4];
            #pragma unroll
            for (int p = 0; p < 4; p++) {
                uint32_t koff = (uint32_t)(p * 16 + (lane & 7) + ((lane & 16) ? 8 : 0)) * RS
                              + ks * 32 + ((lane >> 3) & 1) * 16;
                ldsm4(khf[p], KHb + koff);
                ldsm4(klf[p], KLb + koff);
            }
            #pragma unroll
            for (int p = 0; p < 4; p++)
                #pragma unroll
                for (int q2 = 0; q2 < 2; q2++)
                    mma16816(sacc[p * 2 + q2], qhf[ks], khf[p] + q2 * 2);
            #pragma unroll
            for (int p = 0; p < 4; p++)
                #pragma unroll
                for (int q2 = 0; q2 < 2; q2++)
                    mma16816(sacc[p * 2 + q2], qhf[ks], klf[p] + q2 * 2);
            #pragma unroll
            for (int p = 0; p < 4; p++)
                #pragma unroll
                for (int q2 = 0; q2 < 2; q2++)
                    mma16816(sacc[p * 2 + q2], qlf[ks], khf[p] + q2 * 2);
        }

        // ---- mask -> EPS, p = exp(s), local l accumulate ----
        unsigned wa0 = __ldg(mrow0 + kt * 2), wb0 = __ldg(mrow0 + kt * 2 + 1);
        unsigned wa1 = __ldg(mrow1 + kt * 2), wb1 = __ldg(mrow1 + kt * 2 + 1);
        #pragma unroll
        for (int f = 0; f < 8; f++) {
            int sh = ((f & 3) << 3) + (tp << 1);
            unsigned u0 = ((f < 4) ? wa0 : wb0) >> sh;
            unsigned u1 = ((f < 4) ? wa1 : wb1) >> sh;
            if (!(u0 & 1)) sacc[f][0] = 1e-6f;
            if (!(u0 & 2)) sacc[f][1] = 1e-6f;
            if (!(u1 & 1)) sacc[f][2] = 1e-6f;
            if (!(u1 & 2)) sacc[f][3] = 1e-6f;
            sacc[f][0] = fexp(sacc[f][0]);
            sacc[f][1] = fexp(sacc[f][1]);
            sacc[f][2] = fexp(sacc[f][2]);
            sacc[f][3] = fexp(sacc[f][3]);
            l0 += sacc[f][0] + sacc[f][1];
            l1 += sacc[f][2] + sacc[f][3];
        }

        // ---- O += P V (bf16x3, term-major) ----
        #pragma unroll
        for (int ks = 0; ks < 4; ks++) {
            uint32_t ph[4], pl[4];
            const float* pa = sacc[2 * ks];
            const float* pb = sacc[2 * ks + 1];
            split2(pa[0], pa[1], ph[0], pl[0]);
            split2(pa[2], pa[3], ph[1], pl[1]);
            split2(pb[0], pb[1], ph[2], pl[2]);
            split2(pb[2], pb[3], ph[3], pl[3]);
            uint32_t vhf[4][4], vlf[4][4];
            #pragma unroll
            for (int p = 0; p < 4; p++) {
                uint32_t voff = (uint32_t)(ks * 16 + (lane & 15)) * RS
                              + p * 32 + (lane >> 4) * 16;
                ldsm4t(vhf[p], VHb + voff);
                ldsm4t(vlf[p], VLb + voff);
            }
            #pragma unroll
            for (int p = 0; p < 4; p++)
                #pragma unroll
                for (int q2 = 0; q2 < 2; q2++)
                    mma16816(oacc[p * 2 + q2], ph, vhf[p] + q2 * 2);
            #pragma unroll
            for (int p = 0; p < 4; p++)
                #pragma unroll
                for (int q2 = 0; q2 < 2; q2++)
                    mma16816(oacc[p * 2 + q2], ph, vlf[p] + q2 * 2);
            #pragma unroll
            for (int p = 0; p < 4; p++)
                #pragma unroll
                for (int q2 = 0; q2 < 2; q2++)
                    mma16816(oacc[p * 2 + q2], pl, vhf[p] + q2 * 2);
        }

        __syncthreads();
        if (kt + 2 < 32) issue_tile(kt + 2, st);
        cp_commit();
    }

    // ---- single end-of-loop l reduction across the quad ----
    l0 += __shfl_xor_sync(0xffffffffu, l0, 1);
    l0 += __shfl_xor_sync(0xffffffffu, l0, 2);
    l1 += __shfl_xor_sync(0xffffffffu, l1, 1);
    l1 += __shfl_xor_sync(0xffffffffu, l1, 2);

    float i0 = 1.0f / l0, i1 = 1.0f / l1;
    float* dst0 = g_attn + ((size_t)b * SS + r0g) * DM + h * 64;
    float* dst1 = dst0 + 8 * DM;
    #pragma unroll
    for (int f = 0; f < 8; f++) {
        int c = f * 8 + tp * 2;
        *(float2*)(dst0 + c) = make_float2(oacc[f][0] * i0, oacc[f][1] * i0);
        *(float2*)(dst1 + c) = make_float2(oacc[f][2] * i1, oacc[f][3] * i1);
    }
}

// ---------------------------------------------------------------------------
// LayerNorm (ddof=1, eps added to std)
// ---------------------------------------------------------------------------
__global__ __launch_bounds__(256) void ln_kernel(
    const float* __restrict__ gamma, const float* __restrict__ beta,
    float* __restrict__ out)
{
    int row = blockIdx.x;
    const float* x = g_y + (size_t)row * DM;
    float v[4];
    float sum = 0.f, sq = 0.f;
    #pragma unroll
    for (int i = 0; i < 4; i++) {
        v[i] = x[threadIdx.x + (i << 8)];
        sum += v[i]; sq += v[i] * v[i];
    }
    #pragma unroll
    for (int off = 16; off; off >>= 1) {
        sum += __shfl_xor_sync(0xffffffffu, sum, off);
        sq  += __shfl_xor_sync(0xffffffffu, sq, off);
    }
    __shared__ float s1[8], s2[8];
    int w = threadIdx.x >> 5;
    if ((threadIdx.x & 31) == 0) { s1[w] = sum; s2[w] = sq; }
    __syncthreads();
    if (threadIdx.x < 32) {
        float a  = (threadIdx.x < 8) ? s1[threadIdx.x] : 0.f;
        float bq = (threadIdx.x < 8) ? s2[threadIdx.x] : 0.f;
        #pragma unroll
        for (int off = 4; off; off >>= 1) {
            a  += __shfl_xor_sync(0xffffffffu, a, off);
            bq += __shfl_xor_sync(0xffffffffu, bq, off);
        }
        if (threadIdx.x == 0) { s1[0] = a; s2[0] = bq; }
    }
    __syncthreads();
    float mean = s1[0] * (1.0f / DM);
    float var  = fmaxf((s2[0] - (float)DM * mean * mean) * (1.0f / (DM - 1)), 0.f);
    float inv  = 1.0f / (sqrtf(var) + 1e-6f);
    #pragma unroll
    for (int i = 0; i < 4; i++) {
        int c = threadIdx.x + (i << 8);
        out[(size_t)row * DM + c] = gamma[c] * (v[i] - mean) * inv + beta[c];
    }
}

// ---------------------------------------------------------------------------
extern "C" void kernel_launch(void* const* d_in, const int* in_sizes, int n_in,
                              void* d_out, int out_size) {
    const float* xq    = (const float*)d_in[0];
    const float* xk    = (const float*)d_in[1];
    const float* xv    = (const float*)d_in[2];
    const int*   mask  = (const int*)  d_in[3];
    const float* wq    = (const float*)d_in[4];
    const float* wk    = (const float*)d_in[5];
    const float* wv    = (const float*)d_in[6];
    const float* w0    = (const float*)d_in[7];
    const float* gamma = (const float*)d_in[8];
    const float* beta  = (const float*)d_in[9];
    float* out = (float*)d_out;

    pack_mask_kernel<<<(BB * SS * SS) / 256, 256>>>(mask);

    dim3 pw(DM / 64, DM / 64, 4);
    prep_w_kernel<<<pw, 256>>>(wq, wk, wv, w0);

    cudaFuncSetAttribute(gemm_mma_kernel, cudaFuncAttributeMaxDynamicSharedMemorySize, GEMM_SMEM);
    dim3 gproj(DM / NT, MTOT / MT, 3);
    gemm_mma_kernel<<<gproj, 256, GEMM_SMEM>>>(xq, xk, xv, -1, nullptr);

    cudaFuncSetAttribute(attn_mma_kernel, cudaFuncAttributeMaxDynamicSharedMemorySize, ATTN_SMEM);
    attn_mma_kernel<<<BB * NH * (SS / QROWS), 256, ATTN_SMEM>>>();

    dim3 gout(DM / NT, MTOT / MT, 1);
    gemm_mma_kernel<<<gout, 256, GEMM_SMEM>>>(nullptr, nullptr, nullptr, 3, xq);
    ln_kernel<<<MTOT, 256>>>(gamma, beta, out);
}

// round 14
// speedup vs baseline: 1.0491x; 1.0491x over previous
#include <cuda_runtime.h>
#include <cuda_bf16.h>
#include <stdint.h>

#define BB 4
#define SS 2048
#define DM 1024
#define NH 16
#define DK 64
#define MTOT (BB*SS)   // 8192

// GEMM tiling (mma.sync path)
#define MT 128
#define NT 128
#define KT 32
#define NSLAB (DM/KT)          // 32
#define ROW_STRIDE 80
#define A_BYTES (MT*ROW_STRIDE)
#define STG_BYTES (4*A_BYTES)
#define GEMM_SMEM (2*STG_BYTES)

// Attention tiling
#define QROWS 128
#define KTILE 64
#define RS 144                              // smem row stride (64 bf16 + pad)
#define SM_QH 0
#define SM_QL (QROWS*RS)                    // 18432
#define KV_STG (4*KTILE*RS)                 // 36864 per stage
#define SM_ST(st) (2*QROWS*RS + (st)*KV_STG)
#define ATTN_SMEM (2*QROWS*RS + 2*KV_STG)   // 110592

// ---------------------------------------------------------------------------
// Scratch (static device globals -- no allocations anywhere)
__device__ float g_attn[MTOT*DM];
__device__ float g_y[MTOT*DM];
__device__ unsigned g_mbits[BB*SS*SS/32];
__device__ __nv_bfloat16 g_wt_hi[4][DM*DM];
__device__ __nv_bfloat16 g_wt_lo[4][DM*DM];
__device__ __nv_bfloat16 g_qh[BB*NH*SS*DK], g_ql[BB*NH*SS*DK];
__device__ __nv_bfloat16 g_kh[BB*NH*SS*DK], g_kl[BB*NH*SS*DK];
__device__ __nv_bfloat16 g_vh[BB*NH*SS*DK], g_vl[BB*NH*SS*DK];

// ---------------------------------------------------------------------------
// Helpers (base-target PTX only)
// ---------------------------------------------------------------------------
__device__ __forceinline__ uint32_t smem_u32(const void* p) {
    uint32_t a;
    asm("{ .reg .u64 t; cvta.to.shared.u64 t, %1; cvt.u32.u64 %0, t; }"
        : "=r"(a) : "l"(p));
    return a;
}
__device__ __forceinline__ void ldsm4(uint32_t* r, uint32_t addr) {
    asm volatile("ldmatrix.sync.aligned.m8n8.x4.shared.b16 {%0,%1,%2,%3}, [%4];"
                 : "=r"(r[0]), "=r"(r[1]), "=r"(r[2]), "=r"(r[3]) : "r"(addr));
}
__device__ __forceinline__ void ldsm4t(uint32_t* r, uint32_t addr) {
    asm volatile("ldmatrix.sync.aligned.m8n8.x4.trans.shared.b16 {%0,%1,%2,%3}, [%4];"
                 : "=r"(r[0]), "=r"(r[1]), "=r"(r[2]), "=r"(r[3]) : "r"(addr));
}
__device__ __forceinline__ void mma16816(float* d, const uint32_t* a, const uint32_t* b) {
    asm volatile(
        "mma.sync.aligned.m16n8k16.row.col.f32.bf16.bf16.f32 "
        "{%0,%1,%2,%3}, {%4,%5,%6,%7}, {%8,%9}, {%0,%1,%2,%3};"
        : "+f"(d[0]), "+f"(d[1]), "+f"(d[2]), "+f"(d[3])
        : "r"(a[0]), "r"(a[1]), "r"(a[2]), "r"(a[3]), "r"(b[0]), "r"(b[1]));
}
__device__ __forceinline__ void cp16(uint32_t saddr, const void* gptr) {
    asm volatile("cp.async.cg.shared.global [%0], [%1], 16;"
                 :: "r"(saddr), "l"(gptr) : "memory");
}
__device__ __forceinline__ void cp_commit() { asm volatile("cp.async.commit_group;" ::: "memory"); }
__device__ __forceinline__ void cp_wait0() { asm volatile("cp.async.wait_group 0;" ::: "memory"); }
__device__ __forceinline__ void cp_wait1() { asm volatile("cp.async.wait_group 1;" ::: "memory"); }

// fp32 pair -> bf16x2 hi + bf16x2 lo (x in low half)
__device__ __forceinline__ void split2(float x, float y, uint32_t& hi, uint32_t& lo) {
    __nv_bfloat162 h = __floats2bfloat162_rn(x, y);
    uint32_t hu = *reinterpret_cast<uint32_t*>(&h);
    float hx = __int_as_float(hu << 16);
    float hy = __int_as_float(hu & 0xffff0000u);
    __nv_bfloat162 l = __floats2bfloat162_rn(x - hx, y - hy);
    hi = hu; lo = *reinterpret_cast<uint32_t*>(&l);
}

// Fast exp on the FMA pipe (no MUFU). ~2e-6 rel err.
__device__ __forceinline__ float fexp(float x) {
    float y = fmaxf(x, -80.f) * 1.4426950408889634f;
    float t = y + 12582912.f;
    int   ni = __float_as_int(t) - 0x4B400000;
    float f = y - (t - 12582912.f);
    float p =            1.3333558146e-3f;
    p = fmaf(p, f, 9.6181291057e-3f);
    p = fmaf(p, f, 5.5504108664e-2f);
    p = fmaf(p, f, 2.4022650696e-1f);
    p = fmaf(p, f, 6.9314718056e-1f);
    p = fmaf(p, f, 1.0f);
    return __int_as_float(__float_as_int(p) + (ni << 23));
}

// ---------------------------------------------------------------------------
__global__ void pack_mask_kernel(const int* __restrict__ mask) {
    int i = blockIdx.x * blockDim.x + threadIdx.x;
    unsigned pred = (mask[i] != 0) ? 1u : 0u;
    unsigned w = __ballot_sync(0xffffffffu, pred);
    if ((threadIdx.x & 31) == 0) g_mbits[i >> 5] = w;
}

// ---------------------------------------------------------------------------
// Fused weight prep: grid (16,16,4); z selects which weight matrix.
// ---------------------------------------------------------------------------
__global__ __launch_bounds__(256) void prep_w_kernel(
    const float* __restrict__ W0, const float* __restrict__ W1,
    const float* __restrict__ W2, const float* __restrict__ W3)
{
    __shared__ float ts[64][65];
    int widx = blockIdx.z;
    const float* W = (widx == 0) ? W0 : (widx == 1) ? W1 : (widx == 2) ? W2 : W3;
    int k0 = blockIdx.x * 64, n0 = blockIdx.y * 64;
    int tid = threadIdx.x;
    #pragma unroll
    for (int i = 0; i < 16; i++) {
        int idx = tid + (i << 8);
        int r = idx >> 6, c = idx & 63;
        ts[c][r] = W[(size_t)(k0 + r) * DM + n0 + c];
    }
    __syncthreads();
    __nv_bfloat16* Hi = g_wt_hi[widx];
    __nv_bfloat16* Lo = g_wt_lo[widx];
    #pragma unroll
    for (int i = 0; i < 16; i++) {
        int idx = tid + (i << 8);
        int r = idx >> 6, c = idx & 63;
        float v = ts[r][c];
        __nv_bfloat16 h = __float2bfloat16_rn(v);
        __nv_bfloat16 l = __float2bfloat16_rn(v - __bfloat162float(h));
        size_t o = (size_t)(n0 + r) * DM + k0 + c;
        Hi[o] = h; Lo[o] = l;
    }
}

// ---------------------------------------------------------------------------
// bf16x3 GEMM (mma.sync). Fused projections (gridDim.z==3) / out-proj (mode 3).
// Term-major mma issue (accumulator reuse distance 4).
// ---------------------------------------------------------------------------
__global__ __launch_bounds__(256, 2) void gemm_mma_kernel(
    const float* __restrict__ A0, const float* __restrict__ A1,
    const float* __restrict__ A2, int mode_in, const float* __restrict__ resid)
{
    extern __shared__ char smc[];
    const uint32_t sb = smem_u32(smc);
    const int tid = threadIdx.x, wid = tid >> 5, lane = tid & 31;
    const int bm = blockIdx.y * MT, bn = blockIdx.x * NT;
    const int warp_m = wid >> 2, warp_n = wid & 3;
    const int mode = (mode_in == 3) ? 3 : (int)blockIdx.z;
    const int widx = mode;
    const float* __restrict__ A =
        (mode == 3) ? (const float*)g_attn : (mode == 0) ? A0 : (mode == 1) ? A1 : A2;
    const __nv_bfloat16* __restrict__ BHi = g_wt_hi[widx];
    const __nv_bfloat16* __restrict__ BLo = g_wt_lo[widx];

    float acc[4][4][4];
    #pragma unroll
    for (int i = 0; i < 4; i++)
        #pragma unroll
        for (int j = 0; j < 4; j++)
            #pragma unroll
            for (int c = 0; c < 4; c++) acc[i][j][c] = 0.f;

    const int arow_ld = tid >> 1, acol_ld = (tid & 1) * 16;
    const int a_r = (lane & 15), a_c8 = (lane >> 4) * 8;
    const int b_n = (lane & 7) + ((lane & 16) ? 8 : 0);
    const int b_k8 = ((lane >> 3) & 1) * 8;

    auto issueB = [&](int s, int stage) {
        int k0 = s * KT;
        uint32_t bh = sb + stage * STG_BYTES + 2 * A_BYTES;
        uint32_t bl = bh + A_BYTES;
        #pragma unroll
        for (int i = 0; i < 2; i++) {
            int c = tid + (i << 8);
            int row = c >> 2, seg = c & 3;
            size_t go = (size_t)(bn + row) * DM + k0 + seg * 8;
            uint32_t so = (uint32_t)row * ROW_STRIDE + seg * 16;
            cp16(bh + so, BHi + go);
            cp16(bl + so, BLo + go);
        }
        cp_commit();
    };
    auto ldgA = [&](int s, float* af) {
        const float4* src = (const float4*)(A + (size_t)(bm + arow_ld) * DM + s * KT + acol_ld);
        #pragma unroll
        for (int q = 0; q < 4; q++) ((float4*)af)[q] = src[q];
    };
    auto stsA = [&](int stage, const float* af) {
        uint32_t ah = sb + stage * STG_BYTES;
        uint32_t al = ah + A_BYTES;
        uint32_t ro = (uint32_t)arow_ld * ROW_STRIDE + acol_ld * 2;
        #pragma unroll
        for (int q = 0; q < 4; q++) {
            uint32_t hv0, lv0, hv1, lv1;
            split2(af[4*q], af[4*q+1], hv0, lv0);
            split2(af[4*q+2], af[4*q+3], hv1, lv1);
            uint32_t so = ro + q * 8;
            asm volatile("st.shared.v2.b32 [%0], {%1,%2};" :: "r"(ah + so), "r"(hv0), "r"(hv1) : "memory");
            asm volatile("st.shared.v2.b32 [%0], {%1,%2};" :: "r"(al + so), "r"(lv0), "r"(lv1) : "memory");
        }
    };
    auto compute_half = [&](int stage, int ks) {
        uint32_t ah_b = sb + stage * STG_BYTES;
        uint32_t al_b = ah_b + A_BYTES;
        uint32_t bh_b = ah_b + 2 * A_BYTES;
        uint32_t bl_b = ah_b + 3 * A_BYTES;
        uint32_t bh[8], bl[8];
        #pragma unroll
        for (int p = 0; p < 2; p++) {
            uint32_t bo = (uint32_t)(warp_n * 32 + p * 16 + b_n) * ROW_STRIDE
                        + (ks * 16 + b_k8) * 2;
            ldsm4(bh + 4 * p, bh_b + bo);
            ldsm4(bl + 4 * p, bl_b + bo);
        }
        #pragma unroll
        for (int fi = 0; fi < 4; fi++) {
            uint32_t ao = (uint32_t)(warp_m * 64 + fi * 16 + a_r) * ROW_STRIDE
                        + (ks * 16 + a_c8) * 2;
            uint32_t ahf[4], alf[4];
            ldsm4(ahf, ah_b + ao);
            ldsm4(alf, al_b + ao);
            // term-major: 3 passes, each touching all 4 accumulators
            #pragma unroll
            for (int fj = 0; fj < 4; fj++)
                mma16816(acc[fi][fj], ahf, bh + (fj >> 1) * 4 + (fj & 1) * 2);
            #pragma unroll
            for (int fj = 0; fj < 4; fj++)
                mma16816(acc[fi][fj], ahf, bl + (fj >> 1) * 4 + (fj & 1) * 2);
            #pragma unroll
            for (int fj = 0; fj < 4; fj++)
                mma16816(acc[fi][fj], alf, bh + (fj >> 1) * 4 + (fj & 1) * 2);
        }
    };

    {
        float af[16];
        issueB(0, 0);
        ldgA(0, af);
        stsA(0, af);
        cp_wait0();
        __syncthreads();
    }
    for (int s = 0; s < NSLAB; s++) {
        int stage = s & 1;
        float af[16];
        bool pf = (s + 1 < NSLAB);
        if (pf) { issueB(s + 1, stage ^ 1); ldgA(s + 1, af); }
        compute_half(stage, 0);
        if (pf) stsA(stage ^ 1, af);
        compute_half(stage, 1);
        if (pf) cp_wait0();
        __syncthreads();
    }

    const int t4 = lane >> 2, tp = (lane & 3) * 2;
    #pragma unroll
    for (int fi = 0; fi < 4; fi++) {
        #pragma unroll
        for (int h2 = 0; h2 < 2; h2++) {
            int m = bm + warp_m * 64 + fi * 16 + t4 + h2 * 8;
            if (mode < 3) {
                __nv_bfloat16 *oh, *ol;
                if (mode == 0) { oh = g_qh; ol = g_ql; }
                else if (mode == 1) { oh = g_kh; ol = g_kl; }
                else { oh = g_vh; ol = g_vl; }
                float scale = (mode == 0) ? 0.125f : 1.0f;
                int b = m >> 11, srow = m & (SS - 1);
                #pragma unroll
                for (int fj = 0; fj < 4; fj++) {
                    int n = bn + warp_n * 32 + fj * 8 + tp;
                    int h = n >> 6, d = n & 63;
                    uint32_t hi, lo;
                    split2(acc[fi][fj][h2*2] * scale, acc[fi][fj][h2*2+1] * scale, hi, lo);
                    size_t o = ((((size_t)b * NH + h) * SS) + srow) * DK + d;
                    *(uint32_t*)(oh + o) = hi;
                    *(uint32_t*)(ol + o) = lo;
                }
            } else {
                #pragma unroll
                for (int fj = 0; fj < 4; fj++) {
                    int n = bn + warp_n * 32 + fj * 8 + tp;
                    size_t o = (size_t)m * DM + n;
                    float2 rv = *(const float2*)(resid + o);
                    *(float2*)(g_y + o) = make_float2(acc[fi][fj][h2*2] + rv.x,
                                                      acc[fi][fj][h2*2+1] + rv.y);
                }
            }
        }
    }
}

// ---------------------------------------------------------------------------
// Flash attention (bf16x3, mma.sync), fixed-shift softmax, term-major mma
// ordering, 2 CTAs/SM (regs capped 128, NO Q-hoist -- R13 showed the occ loss
// outweighs the hoist).
// ---------------------------------------------------------------------------
__global__ __launch_bounds__(256, 2) void attn_mma_kernel() {
    extern __shared__ char smc[];
    const uint32_t sb = smem_u32(smc);
    const int tid = threadIdx.x, wp = tid >> 5, lane = tid & 31;
    const int qt = blockIdx.x & 15, h = (blockIdx.x >> 4) & 15, b = blockIdx.x >> 8;
    const size_t base = (size_t)(b * NH + h) * SS * DK;

    const __nv_bfloat16* qh_g = g_qh + base + (size_t)qt * QROWS * DK;
    const __nv_bfloat16* ql_g = g_ql + base + (size_t)qt * QROWS * DK;
    const __nv_bfloat16* kh_g = g_kh + base;
    const __nv_bfloat16* kl_g = g_kl + base;
    const __nv_bfloat16* vh_g = g_vh + base;
    const __nv_bfloat16* vl_g = g_vl + base;

    auto issue_tile = [&](int kt, int st) {
        uint32_t sbase = sb + SM_ST(st);
        #pragma unroll
        for (int i = 0; i < 8; i++) {
            int c = tid + (i << 8);
            int arr = i >> 1;
            int row = (c >> 3) & 63, seg = c & 7;
            const __nv_bfloat16* g =
                (arr == 0) ? kh_g : (arr == 1) ? kl_g : (arr == 2) ? vh_g : vl_g;
            cp16(sbase + arr * (KTILE*RS) + row * RS + seg * 16,
                 g + (size_t)(kt * KTILE + row) * DK + seg * 8);
        }
    };

    {
        #pragma unroll
        for (int i = 0; i < 8; i++) {
            int c = tid + (i << 8);
            int arr = i >> 2;
            int row = (c >> 3) & 127, seg = c & 7;
            const __nv_bfloat16* g = arr ? ql_g : qh_g;
            cp16(sb + (arr ? SM_QL : SM_QH) + row * RS + seg * 16,
                 g + (size_t)row * DK + seg * 8);
        }
        issue_tile(0, 0);
        cp_commit();
        issue_tile(1, 1);
        cp_commit();
    }

    float sacc[8][4], oacc[8][4];
    #pragma unroll
    for (int f = 0; f < 8; f++)
        #pragma unroll
        for (int c = 0; c < 4; c++) oacc[f][c] = 0.f;
    float l0 = 0.f, l1 = 0.f;

    const int t4 = lane >> 2, tp = lane & 3;
    const int r0g = qt * QROWS + wp * 16 + t4;
    const unsigned* mrow0 = g_mbits + ((size_t)b * SS + r0g) * (SS / 32);
    const unsigned* mrow1 = mrow0 + 8 * (SS / 32);

    for (int kt = 0; kt < 32; kt++) {
        int st = kt & 1;
        cp_wait1();
        __syncthreads();
        uint32_t KHb = sb + SM_ST(st);
        uint32_t KLb = KHb + KTILE*RS, VHb = KHb + 2*KTILE*RS, VLb = KHb + 3*KTILE*RS;

        // ---- S = Q K^T (bf16x3, term-major within each ks) ----
        #pragma unroll
        for (int f = 0; f < 8; f++)
            #pragma unroll
            for (int c = 0; c < 4; c++) sacc[f][c] = 0.f;
        #pragma unroll
        for (int ks = 0; ks < 4; ks++) {
            uint32_t qh[4], ql[4];
            uint32_t qoff = (uint32_t)(wp * 16 + (lane & 15)) * RS + ks * 32 + (lane >> 4) * 16;
            ldsm4(qh, sb + SM_QH + qoff);
            ldsm4(ql, sb + SM_QL + qoff);
            uint32_t khf[4][4], klf[4][4];
            #pragma unroll
            for (int p = 0; p < 4; p++) {
                uint32_t koff = (uint32_t)(p * 16 + (lane & 7) + ((lane & 16) ? 8 : 0)) * RS
                              + ks * 32 + ((lane >> 3) & 1) * 16;
                ldsm4(khf[p], KHb + koff);
                ldsm4(klf[p], KLb + koff);
            }
            #pragma unroll
            for (int p = 0; p < 4; p++)
                #pragma unroll
                for (int q2 = 0; q2 < 2; q2++)
                    mma16816(sacc[p * 2 + q2], qh, khf[p] + q2 * 2);
            #pragma unroll
            for (int p = 0; p < 4; p++)
                #pragma unroll
                for (int q2 = 0; q2 < 2; q2++)
                    mma16816(sacc[p * 2 + q2], qh, klf[p] + q2 * 2);
            #pragma unroll
            for (int p = 0; p < 4; p++)
                #pragma unroll
                for (int q2 = 0; q2 < 2; q2++)
                    mma16816(sacc[p * 2 + q2], ql, khf[p] + q2 * 2);
        }

        // ---- mask -> EPS, p = exp(s), local l accumulate ----
        unsigned wa0 = __ldg(mrow0 + kt * 2), wb0 = __ldg(mrow0 + kt * 2 + 1);
        unsigned wa1 = __ldg(mrow1 + kt * 2), wb1 = __ldg(mrow1 + kt * 2 + 1);
        #pragma unroll
        for (int f = 0; f < 8; f++) {
            int sh = ((f & 3) << 3) + (tp << 1);
            unsigned u0 = ((f < 4) ? wa0 : wb0) >> sh;
            unsigned u1 = ((f < 4) ? wa1 : wb1) >> sh;
            if (!(u0 & 1)) sacc[f][0] = 1e-6f;
            if (!(u0 & 2)) sacc[f][1] = 1e-6f;
            if (!(u1 & 1)) sacc[f][2] = 1e-6f;
            if (!(u1 & 2)) sacc[f][3] = 1e-6f;
            sacc[f][0] = fexp(sacc[f][0]);
            sacc[f][1] = fexp(sacc[f][1]);
            sacc[f][2] = fexp(sacc[f][2]);
            sacc[f][3] = fexp(sacc[f][3]);
            l0 += sacc[f][0] + sacc[f][1];
            l1 += sacc[f][2] + sacc[f][3];
        }

        // ---- O += P V (bf16x3, term-major within each ks) ----
        #pragma unroll
        for (int ks = 0; ks < 4; ks++) {
            uint32_t ph[4], pl[4];
            const float* pa = sacc[2 * ks];
            const float* pb = sacc[2 * ks + 1];
            split2(pa[0], pa[1], ph[0], pl[0]);
            split2(pa[2], pa[3], ph[1], pl[1]);
            split2(pb[0], pb[1], ph[2], pl[2]);
            split2(pb[2], pb[3], ph[3], pl[3]);
            uint32_t vhf[4][4], vlf[4][4];
            #pragma unroll
            for (int p = 0; p < 4; p++) {
                uint32_t voff = (uint32_t)(ks * 16 + (lane & 15)) * RS
                              + p * 32 + (lane >> 4) * 16;
                ldsm4t(vhf[p], VHb + voff);
                ldsm4t(vlf[p], VLb + voff);
            }
            #pragma unroll
            for (int p = 0; p < 4; p++)
                #pragma unroll
                for (int q2 = 0; q2 < 2; q2++)
                    mma16816(oacc[p * 2 + q2], ph, vhf[p] + q2 * 2);
            #pragma unroll
            for (int p = 0; p < 4; p++)
                #pragma unroll
                for (int q2 = 0; q2 < 2; q2++)
                    mma16816(oacc[p * 2 + q2], ph, vlf[p] + q2 * 2);
            #pragma unroll
            for (int p = 0; p < 4; p++)
                #pragma unroll
                for (int q2 = 0; q2 < 2; q2++)
                    mma16816(oacc[p * 2 + q2], pl, vhf[p] + q2 * 2);
        }

        __syncthreads();
        if (kt + 2 < 32) issue_tile(kt + 2, st);
        cp_commit();
    }

    // ---- single end-of-loop l reduction across the quad ----
    l0 += __shfl_xor_sync(0xffffffffu, l0, 1);
    l0 += __shfl_xor_sync(0xffffffffu, l0, 2);
    l1 += __shfl_xor_sync(0xffffffffu, l1, 1);
    l1 += __shfl_xor_sync(0xffffffffu, l1, 2);

    float i0 = 1.0f / l0, i1 = 1.0f / l1;
    float* dst0 = g_attn + ((size_t)b * SS + r0g) * DM + h * 64;
    float* dst1 = dst0 + 8 * DM;
    #pragma unroll
    for (int f = 0; f < 8; f++) {
        int c = f * 8 + tp * 2;
        *(float2*)(dst0 + c) = make_float2(oacc[f][0] * i0, oacc[f][1] * i0);
        *(float2*)(dst1 + c) = make_float2(oacc[f][2] * i1, oacc[f][3] * i1);
    }
}

// ---------------------------------------------------------------------------
// LayerNorm (ddof=1, eps added to std)
// ---------------------------------------------------------------------------
__global__ __launch_bounds__(256) void ln_kernel(
    const float* __restrict__ gamma, const float* __restrict__ beta,
    float* __restrict__ out)
{
    int row = blockIdx.x;
    const float* x = g_y + (size_t)row * DM;
    float v[4];
    float sum = 0.f, sq = 0.f;
    #pragma unroll
    for (int i = 0; i < 4; i++) {
        v[i] = x[threadIdx.x + (i << 8)];
        sum += v[i]; sq += v[i] * v[i];
    }
    #pragma unroll
    for (int off = 16; off; off >>= 1) {
        sum += __shfl_xor_sync(0xffffffffu, sum, off);
        sq  += __shfl_xor_sync(0xffffffffu, sq, off);
    }
    __shared__ float s1[8], s2[8];
    int w = threadIdx.x >> 5;
    if ((threadIdx.x & 31) == 0) { s1[w] = sum; s2[w] = sq; }
    __syncthreads();
    if (threadIdx.x < 32) {
        float a  = (threadIdx.x < 8) ? s1[threadIdx.x] : 0.f;
        float bq = (threadIdx.x < 8) ? s2[threadIdx.x] : 0.f;
        #pragma unroll
        for (int off = 4; off; off >>= 1) {
            a  += __shfl_xor_sync(0xffffffffu, a, off);
            bq += __shfl_xor_sync(0xffffffffu, bq, off);
        }
        if (threadIdx.x == 0) { s1[0] = a; s2[0] = bq; }
    }
    __syncthreads();
    float mean = s1[0] * (1.0f / DM);
    float var  = fmaxf((s2[0] - (float)DM * mean * mean) * (1.0f / (DM - 1)), 0.f);
    float inv  = 1.0f / (sqrtf(var) + 1e-6f);
    #pragma unroll
    for (int i = 0; i < 4; i++) {
        int c = threadIdx.x + (i << 8);
        out[(size_t)row * DM + c] = gamma[c] * (v[i] - mean) * inv + beta[c];
    }
}

// ---------------------------------------------------------------------------
extern "C" void kernel_launch(void* const* d_in, const int* in_sizes, int n_in,
                              void* d_out, int out_size) {
    const float* xq    = (const float*)d_in[0];
    const float* xk    = (const float*)d_in[1];
    const float* xv    = (const float*)d_in[2];
    const int*   mask  = (const int*)  d_in[3];
    const float* wq    = (const float*)d_in[4];
    const float* wk    = (const float*)d_in[5];
    const float* wv    = (const float*)d_in[6];
    const float* w0    = (const float*)d_in[7];
    const float* gamma = (const float*)d_in[8];
    const float* beta  = (const float*)d_in[9];
    float* out = (float*)d_out;

    pack_mask_kernel<<<(BB * SS * SS) / 256, 256>>>(mask);

    dim3 pw(DM / 64, DM / 64, 4);
    prep_w_kernel<<<pw, 256>>>(wq, wk, wv, w0);

    cudaFuncSetAttribute(gemm_mma_kernel, cudaFuncAttributeMaxDynamicSharedMemorySize, GEMM_SMEM);
    dim3 gproj(DM / NT, MTOT / MT, 3);
    gemm_mma_kernel<<<gproj, 256, GEMM_SMEM>>>(xq, xk, xv, -1, nullptr);

    cudaFuncSetAttribute(attn_mma_kernel, cudaFuncAttributeMaxDynamicSharedMemorySize, ATTN_SMEM);
    attn_mma_kernel<<<BB * NH * (SS / QROWS), 256, ATTN_SMEM>>>();

    dim3 gout(DM / NT, MTOT / MT, 1);
    gemm_mma_kernel<<<gout, 256, GEMM_SMEM>>>(nullptr, nullptr, nullptr, 3, xq);
    ln_kernel<<<MTOT, 256>>>(gamma, beta, out);
}

// round 15
// speedup vs baseline: 1.1141x; 1.0619x over previous
#include <cuda_runtime.h>
#include <cuda_bf16.h>
#include <stdint.h>

#define BB 4
#define SS 2048
#define DM 1024
#define NH 16
#define DK 64
#define MTOT (BB*SS)   // 8192

// GEMM tiling (mma.sync path)
#define MT 128
#define NT 128
#define KT 32
#define NSLAB (DM/KT)          // 32
#define ROW_STRIDE 80
#define A_BYTES (MT*ROW_STRIDE)
#define STG_BYTES (4*A_BYTES)
#define GEMM_SMEM (2*STG_BYTES)

// Attention tiling. KV stage holds 3 arrays: Kh | Vh | Vl (Kl never loaded --
// QK^T is 2-term bf16; the dropped Q.Kl term is a ~4e-3-absolute random score
// perturbation that averages out in O; V/P lo terms are NOT droppable, their
// error would be coherent ~2e-3 relative).
#define QROWS 128
#define KTILE 64
#define RS 144                              // smem row stride (64 bf16 + pad)
#define SM_QH 0
#define SM_QL (QROWS*RS)                    // 18432
#define KV_STG (3*KTILE*RS)                 // 27648 per stage
#define SM_ST(st) (2*QROWS*RS + (st)*KV_STG)
#define ATTN_SMEM (2*QROWS*RS + 2*KV_STG)   // 92160

// ---------------------------------------------------------------------------
// Scratch (static device globals -- no allocations anywhere)
__device__ float g_attn[MTOT*DM];
__device__ float g_y[MTOT*DM];
__device__ unsigned g_mbits[BB*SS*SS/32];
__device__ __nv_bfloat16 g_wt_hi[4][DM*DM];
__device__ __nv_bfloat16 g_wt_lo[4][DM*DM];
__device__ __nv_bfloat16 g_qh[BB*NH*SS*DK], g_ql[BB*NH*SS*DK];
__device__ __nv_bfloat16 g_kh[BB*NH*SS*DK], g_kl[BB*NH*SS*DK];
__device__ __nv_bfloat16 g_vh[BB*NH*SS*DK], g_vl[BB*NH*SS*DK];

// ---------------------------------------------------------------------------
// Helpers (base-target PTX only)
// ---------------------------------------------------------------------------
__device__ __forceinline__ uint32_t smem_u32(const void* p) {
    uint32_t a;
    asm("{ .reg .u64 t; cvta.to.shared.u64 t, %1; cvt.u32.u64 %0, t; }"
        : "=r"(a) : "l"(p));
    return a;
}
__device__ __forceinline__ void ldsm4(uint32_t* r, uint32_t addr) {
    asm volatile("ldmatrix.sync.aligned.m8n8.x4.shared.b16 {%0,%1,%2,%3}, [%4];"
                 : "=r"(r[0]), "=r"(r[1]), "=r"(r[2]), "=r"(r[3]) : "r"(addr));
}
__device__ __forceinline__ void ldsm4t(uint32_t* r, uint32_t addr) {
    asm volatile("ldmatrix.sync.aligned.m8n8.x4.trans.shared.b16 {%0,%1,%2,%3}, [%4];"
                 : "=r"(r[0]), "=r"(r[1]), "=r"(r[2]), "=r"(r[3]) : "r"(addr));
}
__device__ __forceinline__ void mma16816(float* d, const uint32_t* a, const uint32_t* b) {
    asm volatile(
        "mma.sync.aligned.m16n8k16.row.col.f32.bf16.bf16.f32 "
        "{%0,%1,%2,%3}, {%4,%5,%6,%7}, {%8,%9}, {%0,%1,%2,%3};"
        : "+f"(d[0]), "+f"(d[1]), "+f"(d[2]), "+f"(d[3])
        : "r"(a[0]), "r"(a[1]), "r"(a[2]), "r"(a[3]), "r"(b[0]), "r"(b[1]));
}
__device__ __forceinline__ void cp16(uint32_t saddr, const void* gptr) {
    asm volatile("cp.async.cg.shared.global [%0], [%1], 16;"
                 :: "r"(saddr), "l"(gptr) : "memory");
}
__device__ __forceinline__ void cp_commit() { asm volatile("cp.async.commit_group;" ::: "memory"); }
__device__ __forceinline__ void cp_wait0() { asm volatile("cp.async.wait_group 0;" ::: "memory"); }
__device__ __forceinline__ void cp_wait1() { asm volatile("cp.async.wait_group 1;" ::: "memory"); }

// fp32 pair -> bf16x2 hi + bf16x2 lo (x in low half)
__device__ __forceinline__ void split2(float x, float y, uint32_t& hi, uint32_t& lo) {
    __nv_bfloat162 h = __floats2bfloat162_rn(x, y);
    uint32_t hu = *reinterpret_cast<uint32_t*>(&h);
    float hx = __int_as_float(hu << 16);
    float hy = __int_as_float(hu & 0xffff0000u);
    __nv_bfloat162 l = __floats2bfloat162_rn(x - hx, y - hy);
    hi = hu; lo = *reinterpret_cast<uint32_t*>(&l);
}

// Fast exp on the FMA pipe (no MUFU). ~2e-6 rel err.
__device__ __forceinline__ float fexp(float x) {
    float y = fmaxf(x, -80.f) * 1.4426950408889634f;
    float t = y + 12582912.f;
    int   ni = __float_as_int(t) - 0x4B400000;
    float f = y - (t - 12582912.f);
    float p =            1.3333558146e-3f;
    p = fmaf(p, f, 9.6181291057e-3f);
    p = fmaf(p, f, 5.5504108664e-2f);
    p = fmaf(p, f, 2.4022650696e-1f);
    p = fmaf(p, f, 6.9314718056e-1f);
    p = fmaf(p, f, 1.0f);
    return __int_as_float(__float_as_int(p) + (ni << 23));
}

// ---------------------------------------------------------------------------
__global__ void pack_mask_kernel(const int* __restrict__ mask) {
    int i = blockIdx.x * blockDim.x + threadIdx.x;
    unsigned pred = (mask[i] != 0) ? 1u : 0u;
    unsigned w = __ballot_sync(0xffffffffu, pred);
    if ((threadIdx.x & 31) == 0) g_mbits[i >> 5] = w;
}

// ---------------------------------------------------------------------------
// Fused weight prep: grid (16,16,4); z selects which weight matrix.
// ---------------------------------------------------------------------------
__global__ __launch_bounds__(256) void prep_w_kernel(
    const float* __restrict__ W0, const float* __restrict__ W1,
    const float* __restrict__ W2, const float* __restrict__ W3)
{
    __shared__ float ts[64][65];
    int widx = blockIdx.z;
    const float* W = (widx == 0) ? W0 : (widx == 1) ? W1 : (widx == 2) ? W2 : W3;
    int k0 = blockIdx.x * 64, n0 = blockIdx.y * 64;
    int tid = threadIdx.x;
    #pragma unroll
    for (int i = 0; i < 16; i++) {
        int idx = tid + (i << 8);
        int r = idx >> 6, c = idx & 63;
        ts[c][r] = W[(size_t)(k0 + r) * DM + n0 + c];
    }
    __syncthreads();
    __nv_bfloat16* Hi = g_wt_hi[widx];
    __nv_bfloat16* Lo = g_wt_lo[widx];
    #pragma unroll
    for (int i = 0; i < 16; i++) {
        int idx = tid + (i << 8);
        int r = idx >> 6, c = idx & 63;
        float v = ts[r][c];
        __nv_bfloat16 h = __float2bfloat16_rn(v);
        __nv_bfloat16 l = __float2bfloat16_rn(v - __bfloat162float(h));
        size_t o = (size_t)(n0 + r) * DM + k0 + c;
        Hi[o] = h; Lo[o] = l;
    }
}

// ---------------------------------------------------------------------------
// bf16x3 GEMM (mma.sync). Fused projections (gridDim.z==3) / out-proj (mode 3).
// Term-major mma issue (accumulator reuse distance 4).
// ---------------------------------------------------------------------------
__global__ __launch_bounds__(256, 2) void gemm_mma_kernel(
    const float* __restrict__ A0, const float* __restrict__ A1,
    const float* __restrict__ A2, int mode_in, const float* __restrict__ resid)
{
    extern __shared__ char smc[];
    const uint32_t sb = smem_u32(smc);
    const int tid = threadIdx.x, wid = tid >> 5, lane = tid & 31;
    const int bm = blockIdx.y * MT, bn = blockIdx.x * NT;
    const int warp_m = wid >> 2, warp_n = wid & 3;
    const int mode = (mode_in == 3) ? 3 : (int)blockIdx.z;
    const int widx = mode;
    const float* __restrict__ A =
        (mode == 3) ? (const float*)g_attn : (mode == 0) ? A0 : (mode == 1) ? A1 : A2;
    const __nv_bfloat16* __restrict__ BHi = g_wt_hi[widx];
    const __nv_bfloat16* __restrict__ BLo = g_wt_lo[widx];

    float acc[4][4][4];
    #pragma unroll
    for (int i = 0; i < 4; i++)
        #pragma unroll
        for (int j = 0; j < 4; j++)
            #pragma unroll
            for (int c = 0; c < 4; c++) acc[i][j][c] = 0.f;

    const int arow_ld = tid >> 1, acol_ld = (tid & 1) * 16;
    const int a_r = (lane & 15), a_c8 = (lane >> 4) * 8;
    const int b_n = (lane & 7) + ((lane & 16) ? 8 : 0);
    const int b_k8 = ((lane >> 3) & 1) * 8;

    auto issueB = [&](int s, int stage) {
        int k0 = s * KT;
        uint32_t bh = sb + stage * STG_BYTES + 2 * A_BYTES;
        uint32_t bl = bh + A_BYTES;
        #pragma unroll
        for (int i = 0; i < 2; i++) {
            int c = tid + (i << 8);
            int row = c >> 2, seg = c & 3;
            size_t go = (size_t)(bn + row) * DM + k0 + seg * 8;
            uint32_t so = (uint32_t)row * ROW_STRIDE + seg * 16;
            cp16(bh + so, BHi + go);
            cp16(bl + so, BLo + go);
        }
        cp_commit();
    };
    auto ldgA = [&](int s, float* af) {
        const float4* src = (const float4*)(A + (size_t)(bm + arow_ld) * DM + s * KT + acol_ld);
        #pragma unroll
        for (int q = 0; q < 4; q++) ((float4*)af)[q] = src[q];
    };
    auto stsA = [&](int stage, const float* af) {
        uint32_t ah = sb + stage * STG_BYTES;
        uint32_t al = ah + A_BYTES;
        uint32_t ro = (uint32_t)arow_ld * ROW_STRIDE + acol_ld * 2;
        #pragma unroll
        for (int q = 0; q < 4; q++) {
            uint32_t hv0, lv0, hv1, lv1;
            split2(af[4*q], af[4*q+1], hv0, lv0);
            split2(af[4*q+2], af[4*q+3], hv1, lv1);
            uint32_t so = ro + q * 8;
            asm volatile("st.shared.v2.b32 [%0], {%1,%2};" :: "r"(ah + so), "r"(hv0), "r"(hv1) : "memory");
            asm volatile("st.shared.v2.b32 [%0], {%1,%2};" :: "r"(al + so), "r"(lv0), "r"(lv1) : "memory");
        }
    };
    auto compute_half = [&](int stage, int ks) {
        uint32_t ah_b = sb + stage * STG_BYTES;
        uint32_t al_b = ah_b + A_BYTES;
        uint32_t bh_b = ah_b + 2 * A_BYTES;
        uint32_t bl_b = ah_b + 3 * A_BYTES;
        uint32_t bh[8], bl[8];
        #pragma unroll
        for (int p = 0; p < 2; p++) {
            uint32_t bo = (uint32_t)(warp_n * 32 + p * 16 + b_n) * ROW_STRIDE
                        + (ks * 16 + b_k8) * 2;
            ldsm4(bh + 4 * p, bh_b + bo);
            ldsm4(bl + 4 * p, bl_b + bo);
        }
        #pragma unroll
        for (int fi = 0; fi < 4; fi++) {
            uint32_t ao = (uint32_t)(warp_m * 64 + fi * 16 + a_r) * ROW_STRIDE
                        + (ks * 16 + a_c8) * 2;
            uint32_t ahf[4], alf[4];
            ldsm4(ahf, ah_b + ao);
            ldsm4(alf, al_b + ao);
            // term-major: 3 passes, each touching all 4 accumulators
            #pragma unroll
            for (int fj = 0; fj < 4; fj++)
                mma16816(acc[fi][fj], ahf, bh + (fj >> 1) * 4 + (fj & 1) * 2);
            #pragma unroll
            for (int fj = 0; fj < 4; fj++)
                mma16816(acc[fi][fj], ahf, bl + (fj >> 1) * 4 + (fj & 1) * 2);
            #pragma unroll
            for (int fj = 0; fj < 4; fj++)
                mma16816(acc[fi][fj], alf, bh + (fj >> 1) * 4 + (fj & 1) * 2);
        }
    };

    {
        float af[16];
        issueB(0, 0);
        ldgA(0, af);
        stsA(0, af);
        cp_wait0();
        __syncthreads();
    }
    for (int s = 0; s < NSLAB; s++) {
        int stage = s & 1;
        float af[16];
        bool pf = (s + 1 < NSLAB);
        if (pf) { issueB(s + 1, stage ^ 1); ldgA(s + 1, af); }
        compute_half(stage, 0);
        if (pf) stsA(stage ^ 1, af);
        compute_half(stage, 1);
        if (pf) cp_wait0();
        __syncthreads();
    }

    const int t4 = lane >> 2, tp = (lane & 3) * 2;
    #pragma unroll
    for (int fi = 0; fi < 4; fi++) {
        #pragma unroll
        for (int h2 = 0; h2 < 2; h2++) {
            int m = bm + warp_m * 64 + fi * 16 + t4 + h2 * 8;
            if (mode < 3) {
                __nv_bfloat16 *oh, *ol;
                if (mode == 0) { oh = g_qh; ol = g_ql; }
                else if (mode == 1) { oh = g_kh; ol = g_kl; }
                else { oh = g_vh; ol = g_vl; }
                float scale = (mode == 0) ? 0.125f : 1.0f;
                int b = m >> 11, srow = m & (SS - 1);
                #pragma unroll
                for (int fj = 0; fj < 4; fj++) {
                    int n = bn + warp_n * 32 + fj * 8 + tp;
                    int h = n >> 6, d = n & 63;
                    uint32_t hi, lo;
                    split2(acc[fi][fj][h2*2] * scale, acc[fi][fj][h2*2+1] * scale, hi, lo);
                    size_t o = ((((size_t)b * NH + h) * SS) + srow) * DK + d;
                    *(uint32_t*)(oh + o) = hi;
                    *(uint32_t*)(ol + o) = lo;
                }
            } else {
                #pragma unroll
                for (int fj = 0; fj < 4; fj++) {
                    int n = bn + warp_n * 32 + fj * 8 + tp;
                    size_t o = (size_t)m * DM + n;
                    float2 rv = *(const float2*)(resid + o);
                    *(float2*)(g_y + o) = make_float2(acc[fi][fj][h2*2] + rv.x,
                                                      acc[fi][fj][h2*2+1] + rv.y);
                }
            }
        }
    }
}

// ---------------------------------------------------------------------------
// Flash attention: QK^T 2-term bf16 (Kl dropped), P.V 3-term bf16x3,
// fixed-shift softmax, term-major mma, 2 CTAs/SM.
// ---------------------------------------------------------------------------
__global__ __launch_bounds__(256, 2) void attn_mma_kernel() {
    extern __shared__ char smc[];
    const uint32_t sb = smem_u32(smc);
    const int tid = threadIdx.x, wp = tid >> 5, lane = tid & 31;
    const int qt = blockIdx.x & 15, h = (blockIdx.x >> 4) & 15, b = blockIdx.x >> 8;
    const size_t base = (size_t)(b * NH + h) * SS * DK;

    const __nv_bfloat16* qh_g = g_qh + base + (size_t)qt * QROWS * DK;
    const __nv_bfloat16* ql_g = g_ql + base + (size_t)qt * QROWS * DK;
    const __nv_bfloat16* kh_g = g_kh + base;
    const __nv_bfloat16* vh_g = g_vh + base;
    const __nv_bfloat16* vl_g = g_vl + base;

    // KV stage: Kh | Vh | Vl, 64 rows x 128B each -> 6 cp16 per thread
    auto issue_tile = [&](int kt, int st) {
        uint32_t sbase = sb + SM_ST(st);
        #pragma unroll
        for (int i = 0; i < 6; i++) {
            int c = tid + (i << 8);
            int arr = i >> 1;                 // 0:Kh 1:Vh 2:Vl (c>>9 == i>>1)
            int row = (c >> 3) & 63, seg = c & 7;
            const __nv_bfloat16* g = (arr == 0) ? kh_g : (arr == 1) ? vh_g : vl_g;
            cp16(sbase + arr * (KTILE*RS) + row * RS + seg * 16,
                 g + (size_t)(kt * KTILE + row) * DK + seg * 8);
        }
    };

    {
        #pragma unroll
        for (int i = 0; i < 8; i++) {
            int c = tid + (i << 8);
            int arr = i >> 2;
            int row = (c >> 3) & 127, seg = c & 7;
            const __nv_bfloat16* g = arr ? ql_g : qh_g;
            cp16(sb + (arr ? SM_QL : SM_QH) + row * RS + seg * 16,
                 g + (size_t)row * DK + seg * 8);
        }
        issue_tile(0, 0);
        cp_commit();
        issue_tile(1, 1);
        cp_commit();
    }

    float sacc[8][4], oacc[8][4];
    #pragma unroll
    for (int f = 0; f < 8; f++)
        #pragma unroll
        for (int c = 0; c < 4; c++) oacc[f][c] = 0.f;
    float l0 = 0.f, l1 = 0.f;

    const int t4 = lane >> 2, tp = lane & 3;
    const int r0g = qt * QROWS + wp * 16 + t4;
    const unsigned* mrow0 = g_mbits + ((size_t)b * SS + r0g) * (SS / 32);
    const unsigned* mrow1 = mrow0 + 8 * (SS / 32);

    for (int kt = 0; kt < 32; kt++) {
        int st = kt & 1;
        cp_wait1();
        __syncthreads();
        uint32_t KHb = sb + SM_ST(st);
        uint32_t VHb = KHb + KTILE*RS, VLb = KHb + 2*KTILE*RS;

        // ---- S = Q K^T (2-term: Qh.Kh + Ql.Kh) ----
        #pragma unroll
        for (int f = 0; f < 8; f++)
            #pragma unroll
            for (int c = 0; c < 4; c++) sacc[f][c] = 0.f;
        #pragma unroll
        for (int ks = 0; ks < 4; ks++) {
            uint32_t qh[4], ql[4];
            uint32_t qoff = (uint32_t)(wp * 16 + (lane & 15)) * RS + ks * 32 + (lane >> 4) * 16;
            ldsm4(qh, sb + SM_QH + qoff);
            ldsm4(ql, sb + SM_QL + qoff);
            uint32_t khf[4][4];
            #pragma unroll
            for (int p = 0; p < 4; p++) {
                uint32_t koff = (uint32_t)(p * 16 + (lane & 7) + ((lane & 16) ? 8 : 0)) * RS
                              + ks * 32 + ((lane >> 3) & 1) * 16;
                ldsm4(khf[p], KHb + koff);
            }
            #pragma unroll
            for (int p = 0; p < 4; p++)
                #pragma unroll
                for (int q2 = 0; q2 < 2; q2++)
                    mma16816(sacc[p * 2 + q2], qh, khf[p] + q2 * 2);
            #pragma unroll
            for (int p = 0; p < 4; p++)
                #pragma unroll
                for (int q2 = 0; q2 < 2; q2++)
                    mma16816(sacc[p * 2 + q2], ql, khf[p] + q2 * 2);
        }

        // ---- mask -> EPS, p = exp(s), local l accumulate ----
        unsigned wa0 = __ldg(mrow0 + kt * 2), wb0 = __ldg(mrow0 + kt * 2 + 1);
        unsigned wa1 = __ldg(mrow1 + kt * 2), wb1 = __ldg(mrow1 + kt * 2 + 1);
        #pragma unroll
        for (int f = 0; f < 8; f++) {
            int sh = ((f & 3) << 3) + (tp << 1);
            unsigned u0 = ((f < 4) ? wa0 : wb0) >> sh;
            unsigned u1 = ((f < 4) ? wa1 : wb1) >> sh;
            if (!(u0 & 1)) sacc[f][0] = 1e-6f;
            if (!(u0 & 2)) sacc[f][1] = 1e-6f;
            if (!(u1 & 1)) sacc[f][2] = 1e-6f;
            if (!(u1 & 2)) sacc[f][3] = 1e-6f;
            sacc[f][0] = fexp(sacc[f][0]);
            sacc[f][1] = fexp(sacc[f][1]);
            sacc[f][2] = fexp(sacc[f][2]);
            sacc[f][3] = fexp(sacc[f][3]);
            l0 += sacc[f][0] + sacc[f][1];
            l1 += sacc[f][2] + sacc[f][3];
        }

        // ---- O += P V (3-term: Ph.Vh + Ph.Vl + Pl.Vh, term-major) ----
        #pragma unroll
        for (int ks = 0; ks < 4; ks++) {
            uint32_t ph[4], pl[4];
            const float* pa = sacc[2 * ks];
            const float* pb = sacc[2 * ks + 1];
            split2(pa[0], pa[1], ph[0], pl[0]);
            split2(pa[2], pa[3], ph[1], pl[1]);
            split2(pb[0], pb[1], ph[2], pl[2]);
            split2(pb[2], pb[3], ph[3], pl[3]);
            uint32_t vhf[4][4], vlf[4][4];
            #pragma unroll
            for (int p = 0; p < 4; p++) {
                uint32_t voff = (uint32_t)(ks * 16 + (lane & 15)) * RS
                              + p * 32 + (lane >> 4) * 16;
                ldsm4t(vhf[p], VHb + voff);
                ldsm4t(vlf[p], VLb + voff);
            }
            #pragma unroll
            for (int p = 0; p < 4; p++)
                #pragma unroll
                for (int q2 = 0; q2 < 2; q2++)
                    mma16816(oacc[p * 2 + q2], ph, vhf[p] + q2 * 2);
            #pragma unroll
            for (int p = 0; p < 4; p++)
                #pragma unroll
                for (int q2 = 0; q2 < 2; q2++)
                    mma16816(oacc[p * 2 + q2], ph, vlf[p] + q2 * 2);
            #pragma unroll
            for (int p = 0; p < 4; p++)
                #pragma unroll
                for (int q2 = 0; q2 < 2; q2++)
                    mma16816(oacc[p * 2 + q2], pl, vhf[p] + q2 * 2);
        }

        __syncthreads();
        if (kt + 2 < 32) issue_tile(kt + 2, st);
        cp_commit();
    }

    // ---- single end-of-loop l reduction across the quad ----
    l0 += __shfl_xor_sync(0xffffffffu, l0, 1);
    l0 += __shfl_xor_sync(0xffffffffu, l0, 2);
    l1 += __shfl_xor_sync(0xffffffffu, l1, 1);
    l1 += __shfl_xor_sync(0xffffffffu, l1, 2);

    float i0 = 1.0f / l0, i1 = 1.0f / l1;
    float* dst0 = g_attn + ((size_t)b * SS + r0g) * DM + h * 64;
    float* dst1 = dst0 + 8 * DM;
    #pragma unroll
    for (int f = 0; f < 8; f++) {
        int c = f * 8 + tp * 2;
        *(float2*)(dst0 + c) = make_float2(oacc[f][0] * i0, oacc[f][1] * i0);
        *(float2*)(dst1 + c) = make_float2(oacc[f][2] * i1, oacc[f][3] * i1);
    }
}

// ---------------------------------------------------------------------------
// LayerNorm (ddof=1, eps added to std)
// ---------------------------------------------------------------------------
__global__ __launch_bounds__(256) void ln_kernel(
    const float* __restrict__ gamma, const float* __restrict__ beta,
    float* __restrict__ out)
{
    int row = blockIdx.x;
    const float* x = g_y + (size_t)row * DM;
    float v[4];
    float sum = 0.f, sq = 0.f;
    #pragma unroll
    for (int i = 0; i < 4; i++) {
        v[i] = x[threadIdx.x + (i << 8)];
        sum += v[i]; sq += v[i] * v[i];
    }
    #pragma unroll
    for (int off = 16; off; off >>= 1) {
        sum += __shfl_xor_sync(0xffffffffu, sum, off);
        sq  += __shfl_xor_sync(0xffffffffu, sq, off);
    }
    __shared__ float s1[8], s2[8];
    int w = threadIdx.x >> 5;
    if ((threadIdx.x & 31) == 0) { s1[w] = sum; s2[w] = sq; }
    __syncthreads();
    if (threadIdx.x < 32) {
        float a  = (threadIdx.x < 8) ? s1[threadIdx.x] : 0.f;
        float bq = (threadIdx.x < 8) ? s2[threadIdx.x] : 0.f;
        #pragma unroll
        for (int off = 4; off; off >>= 1) {
            a  += __shfl_xor_sync(0xffffffffu, a, off);
            bq += __shfl_xor_sync(0xffffffffu, bq, off);
        }
        if (threadIdx.x == 0) { s1[0] = a; s2[0] = bq; }
    }
    __syncthreads();
    float mean = s1[0] * (1.0f / DM);
    float var  = fmaxf((s2[0] - (float)DM * mean * mean) * (1.0f / (DM - 1)), 0.f);
    float inv  = 1.0f / (sqrtf(var) + 1e-6f);
    #pragma unroll
    for (int i = 0; i < 4; i++) {
        int c = threadIdx.x + (i << 8);
        out[(size_t)row * DM + c] = gamma[c] * (v[i] - mean) * inv + beta[c];
    }
}

// ---------------------------------------------------------------------------
extern "C" void kernel_launch(void* const* d_in, const int* in_sizes, int n_in,
                              void* d_out, int out_size) {
    const float* xq    = (const float*)d_in[0];
    const float* xk    = (const float*)d_in[1];
    const float* xv    = (const float*)d_in[2];
    const int*   mask  = (const int*)  d_in[3];
    const float* wq    = (const float*)d_in[4];
    const float* wk    = (const float*)d_in[5];
    const float* wv    = (const float*)d_in[6];
    const float* w0    = (const float*)d_in[7];
    const float* gamma = (const float*)d_in[8];
    const float* beta  = (const float*)d_in[9];
    float* out = (float*)d_out;

    pack_mask_kernel<<<(BB * SS * SS) / 256, 256>>>(mask);

    dim3 pw(DM / 64, DM / 64, 4);
    prep_w_kernel<<<pw, 256>>>(wq, wk, wv, w0);

    cudaFuncSetAttribute(gemm_mma_kernel, cudaFuncAttributeMaxDynamicSharedMemorySize, GEMM_SMEM);
    dim3 gproj(DM / NT, MTOT / MT, 3);
    gemm_mma_kernel<<<gproj, 256, GEMM_SMEM>>>(xq, xk, xv, -1, nullptr);

    cudaFuncSetAttribute(attn_mma_kernel, cudaFuncAttributeMaxDynamicSharedMemorySize, ATTN_SMEM);
    attn_mma_kernel<<<BB * NH * (SS / QROWS), 256, ATTN_SMEM>>>();

    dim3 gout(DM / NT, MTOT / MT, 1);
    gemm_mma_kernel<<<gout, 256, GEMM_SMEM>>>(nullptr, nullptr, nullptr, 3, xq);
    ln_kernel<<<MTOT, 256>>>(gamma, beta, out);
}

// round 16
// speedup vs baseline: 1.1221x; 1.0072x over previous
#include <cuda_runtime.h>
#include <cuda_bf16.h>
#include <stdint.h>

#define BB 4
#define SS 2048
#define DM 1024
#define NH 16
#define DK 64
#define MTOT (BB*SS)   // 8192

// GEMM tiling (mma.sync path)
#define MT 128
#define NT 128
#define KT 32
#define NSLAB (DM/KT)          // 32
#define ROW_STRIDE 80
#define A_BYTES (MT*ROW_STRIDE)
#define STG_BYTES (4*A_BYTES)
#define GEMM_SMEM (2*STG_BYTES)

// Attention tiling. KV stage: Kh | Vh | Vl (Kl never loaded; QK^T 2-term).
#define QROWS 128
#define KTILE 64
#define RS 144
#define SM_QH 0
#define SM_QL (QROWS*RS)
#define KV_STG (3*KTILE*RS)
#define SM_ST(st) (2*QROWS*RS + (st)*KV_STG)
#define ATTN_SMEM (2*QROWS*RS + 2*KV_STG)   // 92160

// Q prescale folds 1/sqrt(64) AND log2(e): scores arrive in exp2 domain.
#define QSCALE 0.18033688011112042f
// EPS mask value in the log2 domain: 1e-6 * log2(e)
#define EPS_L2 1.4426950e-6f

// ---------------------------------------------------------------------------
__device__ float g_attn[MTOT*DM];
__device__ float g_y[MTOT*DM];
__device__ unsigned g_mbits[BB*SS*SS/32];
__device__ __nv_bfloat16 g_wt_hi[4][DM*DM];
__device__ __nv_bfloat16 g_wt_lo[4][DM*DM];
__device__ __nv_bfloat16 g_qh[BB*NH*SS*DK], g_ql[BB*NH*SS*DK];
__device__ __nv_bfloat16 g_kh[BB*NH*SS*DK], g_kl[BB*NH*SS*DK];
__device__ __nv_bfloat16 g_vh[BB*NH*SS*DK], g_vl[BB*NH*SS*DK];

// ---------------------------------------------------------------------------
__device__ __forceinline__ uint32_t smem_u32(const void* p) {
    uint32_t a;
    asm("{ .reg .u64 t; cvta.to.shared.u64 t, %1; cvt.u32.u64 %0, t; }"
        : "=r"(a) : "l"(p));
    return a;
}
__device__ __forceinline__ void ldsm4(uint32_t* r, uint32_t addr) {
    asm volatile("ldmatrix.sync.aligned.m8n8.x4.shared.b16 {%0,%1,%2,%3}, [%4];"
                 : "=r"(r[0]), "=r"(r[1]), "=r"(r[2]), "=r"(r[3]) : "r"(addr));
}
__device__ __forceinline__ void ldsm4t(uint32_t* r, uint32_t addr) {
    asm volatile("ldmatrix.sync.aligned.m8n8.x4.trans.shared.b16 {%0,%1,%2,%3}, [%4];"
                 : "=r"(r[0]), "=r"(r[1]), "=r"(r[2]), "=r"(r[3]) : "r"(addr));
}
__device__ __forceinline__ void mma16816(float* d, const uint32_t* a, const uint32_t* b) {
    asm volatile(
        "mma.sync.aligned.m16n8k16.row.col.f32.bf16.bf16.f32 "
        "{%0,%1,%2,%3}, {%4,%5,%6,%7}, {%8,%9}, {%0,%1,%2,%3};"
        : "+f"(d[0]), "+f"(d[1]), "+f"(d[2]), "+f"(d[3])
        : "r"(a[0]), "r"(a[1]), "r"(a[2]), "r"(a[3]), "r"(b[0]), "r"(b[1]));
}
__device__ __forceinline__ void cp16(uint32_t saddr, const void* gptr) {
    asm volatile("cp.async.cg.shared.global [%0], [%1], 16;"
                 :: "r"(saddr), "l"(gptr) : "memory");
}
__device__ __forceinline__ void cp_commit() { asm volatile("cp.async.commit_group;" ::: "memory"); }
__device__ __forceinline__ void cp_wait0() { asm volatile("cp.async.wait_group 0;" ::: "memory"); }
__device__ __forceinline__ void cp_wait1() { asm volatile("cp.async.wait_group 1;" ::: "memory"); }

// Round-to-nearest split (used where the lo term may be DROPPED downstream:
// K epilogue; also all cold epilogues / prep).
__device__ __forceinline__ void split2r(float x, float y, uint32_t& hi, uint32_t& lo) {
    __nv_bfloat162 h = __floats2bfloat162_rn(x, y);
    uint32_t hu = *reinterpret_cast<uint32_t*>(&h);
    float hx = __int_as_float(hu << 16);
    float hy = __int_as_float(hu & 0xffff0000u);
    __nv_bfloat162 l = __floats2bfloat162_rn(x - hx, y - hy);
    hi = hu; lo = *reinterpret_cast<uint32_t*>(&l);
}
// Truncation split (cheaper; exact hi+lo -- use ONLY where the lo term is
// retained: A mainloop split, P split).
__device__ __forceinline__ void split2t(float x, float y, uint32_t& hi, uint32_t& lo) {
    uint32_t bx = __float_as_uint(x), by = __float_as_uint(y);
    hi = __byte_perm(bx, by, 0x7632);
    float hx = __uint_as_float(bx & 0xffff0000u);
    float hy = __uint_as_float(by & 0xffff0000u);
    __nv_bfloat162 l = __floats2bfloat162_rn(x - hx, y - hy);
    lo = *reinterpret_cast<uint32_t*>(&l);
}

// exp2 on the FMA pipe, degree-4, no clamp (inputs bounded |y| < ~25).
__device__ __forceinline__ float fexp2(float y) {
    float t = y + 12582912.f;
    int   ni = __float_as_int(t) - 0x4B400000;
    float f = y - (t - 12582912.f);
    float p =            9.6181291057e-3f;
    p = fmaf(p, f, 5.5504108664e-2f);
    p = fmaf(p, f, 2.4022650696e-1f);
    p = fmaf(p, f, 6.9314718056e-1f);
    p = fmaf(p, f, 1.0f);
    return __int_as_float(__float_as_int(p) + (ni << 23));
}

// ---------------------------------------------------------------------------
__global__ void pack_mask_kernel(const int* __restrict__ mask) {
    int i = blockIdx.x * blockDim.x + threadIdx.x;
    unsigned pred = (mask[i] != 0) ? 1u : 0u;
    unsigned w = __ballot_sync(0xffffffffu, pred);
    if ((threadIdx.x & 31) == 0) g_mbits[i >> 5] = w;
}

// ---------------------------------------------------------------------------
__global__ __launch_bounds__(256) void prep_w_kernel(
    const float* __restrict__ W0, const float* __restrict__ W1,
    const float* __restrict__ W2, const float* __restrict__ W3)
{
    __shared__ float ts[64][65];
    int widx = blockIdx.z;
    const float* W = (widx == 0) ? W0 : (widx == 1) ? W1 : (widx == 2) ? W2 : W3;
    int k0 = blockIdx.x * 64, n0 = blockIdx.y * 64;
    int tid = threadIdx.x;
    #pragma unroll
    for (int i = 0; i < 16; i++) {
        int idx = tid + (i << 8);
        int r = idx >> 6, c = idx & 63;
        ts[c][r] = W[(size_t)(k0 + r) * DM + n0 + c];
    }
    __syncthreads();
    __nv_bfloat16* Hi = g_wt_hi[widx];
    __nv_bfloat16* Lo = g_wt_lo[widx];
    #pragma unroll
    for (int i = 0; i < 16; i++) {
        int idx = tid + (i << 8);
        int r = idx >> 6, c = idx & 63;
        float v = ts[r][c];
        __nv_bfloat16 h = __float2bfloat16_rn(v);
        __nv_bfloat16 l = __float2bfloat16_rn(v - __bfloat162float(h));
        size_t o = (size_t)(n0 + r) * DM + k0 + c;
        Hi[o] = h; Lo[o] = l;
    }
}

// ---------------------------------------------------------------------------
// bf16x3 GEMM (mma.sync). Fused projections (gridDim.z==3) / out-proj (mode 3).
// ---------------------------------------------------------------------------
__global__ __launch_bounds__(256, 2) void gemm_mma_kernel(
    const float* __restrict__ A0, const float* __restrict__ A1,
    const float* __restrict__ A2, int mode_in, const float* __restrict__ resid)
{
    extern __shared__ char smc[];
    const uint32_t sb = smem_u32(smc);
    const int tid = threadIdx.x, wid = tid >> 5, lane = tid & 31;
    const int bm = blockIdx.y * MT, bn = blockIdx.x * NT;
    const int warp_m = wid >> 2, warp_n = wid & 3;
    const int mode = (mode_in == 3) ? 3 : (int)blockIdx.z;
    const int widx = mode;
    const float* __restrict__ A =
        (mode == 3) ? (const float*)g_attn : (mode == 0) ? A0 : (mode == 1) ? A1 : A2;
    const __nv_bfloat16* __restrict__ BHi = g_wt_hi[widx];
    const __nv_bfloat16* __restrict__ BLo = g_wt_lo[widx];

    float acc[4][4][4];
    #pragma unroll
    for (int i = 0; i < 4; i++)
        #pragma unroll
        for (int j = 0; j < 4; j++)
            #pragma unroll
            for (int c = 0; c < 4; c++) acc[i][j][c] = 0.f;

    const int arow_ld = tid >> 1, acol_ld = (tid & 1) * 16;
    const int a_r = (lane & 15), a_c8 = (lane >> 4) * 8;
    const int b_n = (lane & 7) + ((lane & 16) ? 8 : 0);
    const int b_k8 = ((lane >> 3) & 1) * 8;

    auto issueB = [&](int s, int stage) {
        int k0 = s * KT;
        uint32_t bh = sb + stage * STG_BYTES + 2 * A_BYTES;
        uint32_t bl = bh + A_BYTES;
        #pragma unroll
        for (int i = 0; i < 2; i++) {
            int c = tid + (i << 8);
            int row = c >> 2, seg = c & 3;
            size_t go = (size_t)(bn + row) * DM + k0 + seg * 8;
            uint32_t so = (uint32_t)row * ROW_STRIDE + seg * 16;
            cp16(bh + so, BHi + go);
            cp16(bl + so, BLo + go);
        }
        cp_commit();
    };
    auto ldgA = [&](int s, float* af) {
        const float4* src = (const float4*)(A + (size_t)(bm + arow_ld) * DM + s * KT + acol_ld);
        #pragma unroll
        for (int q = 0; q < 4; q++) ((float4*)af)[q] = src[q];
    };
    auto stsA = [&](int stage, const float* af) {
        uint32_t ah = sb + stage * STG_BYTES;
        uint32_t al = ah + A_BYTES;
        uint32_t ro = (uint32_t)arow_ld * ROW_STRIDE + acol_ld * 2;
        #pragma unroll
        for (int q = 0; q < 4; q++) {
            uint32_t hv0, lv0, hv1, lv1;
            split2t(af[4*q], af[4*q+1], hv0, lv0);     // lo retained -> trunc ok
            split2t(af[4*q+2], af[4*q+3], hv1, lv1);
            uint32_t so = ro + q * 8;
            asm volatile("st.shared.v2.b32 [%0], {%1,%2};" :: "r"(ah + so), "r"(hv0), "r"(hv1) : "memory");
            asm volatile("st.shared.v2.b32 [%0], {%1,%2};" :: "r"(al + so), "r"(lv0), "r"(lv1) : "memory");
        }
    };
    auto compute_half = [&](int stage, int ks) {
        uint32_t ah_b = sb + stage * STG_BYTES;
        uint32_t al_b = ah_b + A_BYTES;
        uint32_t bh_b = ah_b + 2 * A_BYTES;
        uint32_t bl_b = ah_b + 3 * A_BYTES;
        uint32_t bh[8], bl[8];
        #pragma unroll
        for (int p = 0; p < 2; p++) {
            uint32_t bo = (uint32_t)(warp_n * 32 + p * 16 + b_n) * ROW_STRIDE
                        + (ks * 16 + b_k8) * 2;
            ldsm4(bh + 4 * p, bh_b + bo);
            ldsm4(bl + 4 * p, bl_b + bo);
        }
        #pragma unroll
        for (int fi = 0; fi < 4; fi++) {
            uint32_t ao = (uint32_t)(warp_m * 64 + fi * 16 + a_r) * ROW_STRIDE
                        + (ks * 16 + a_c8) * 2;
            uint32_t ahf[4], alf[4];
            ldsm4(ahf, ah_b + ao);
            ldsm4(alf, al_b + ao);
            #pragma unroll
            for (int fj = 0; fj < 4; fj++)
                mma16816(acc[fi][fj], ahf, bh + (fj >> 1) * 4 + (fj & 1) * 2);
            #pragma unroll
            for (int fj = 0; fj < 4; fj++)
                mma16816(acc[fi][fj], ahf, bl + (fj >> 1) * 4 + (fj & 1) * 2);
            #pragma unroll
            for (int fj = 0; fj < 4; fj++)
                mma16816(acc[fi][fj], alf, bh + (fj >> 1) * 4 + (fj & 1) * 2);
        }
    };

    {
        float af[16];
        issueB(0, 0);
        ldgA(0, af);
        stsA(0, af);
        cp_wait0();
        __syncthreads();
    }
    for (int s = 0; s < NSLAB; s++) {
        int stage = s & 1;
        float af[16];
        bool pf = (s + 1 < NSLAB);
        if (pf) { issueB(s + 1, stage ^ 1); ldgA(s + 1, af); }
        compute_half(stage, 0);
        if (pf) stsA(stage ^ 1, af);
        compute_half(stage, 1);
        if (pf) cp_wait0();
        __syncthreads();
    }

    const int t4 = lane >> 2, tp = (lane & 3) * 2;
    #pragma unroll
    for (int fi = 0; fi < 4; fi++) {
        #pragma unroll
        for (int h2 = 0; h2 < 2; h2++) {
            int m = bm + warp_m * 64 + fi * 16 + t4 + h2 * 8;
            if (mode < 3) {
                __nv_bfloat16 *oh, *ol;
                if (mode == 0) { oh = g_qh; ol = g_ql; }
                else if (mode == 1) { oh = g_kh; ol = g_kl; }
                else { oh = g_vh; ol = g_vl; }
                float scale = (mode == 0) ? QSCALE : 1.0f;
                int b = m >> 11, srow = m & (SS - 1);
                #pragma unroll
                for (int fj = 0; fj < 4; fj++) {
                    int n = bn + warp_n * 32 + fj * 8 + tp;
                    int h = n >> 6, d = n & 63;
                    uint32_t hi, lo;
                    // rn split here (K's lo term is dropped in attention --
                    // hi must be best-rounded).
                    split2r(acc[fi][fj][h2*2] * scale, acc[fi][fj][h2*2+1] * scale, hi, lo);
                    size_t o = ((((size_t)b * NH + h) * SS) + srow) * DK + d;
                    *(uint32_t*)(oh + o) = hi;
                    *(uint32_t*)(ol + o) = lo;
                }
            } else {
                #pragma unroll
                for (int fj = 0; fj < 4; fj++) {
                    int n = bn + warp_n * 32 + fj * 8 + tp;
                    size_t o = (size_t)m * DM + n;
                    float2 rv = *(const float2*)(resid + o);
                    *(float2*)(g_y + o) = make_float2(acc[fi][fj][h2*2] + rv.x,
                                                      acc[fi][fj][h2*2+1] + rv.y);
                }
            }
        }
    }
}

// ---------------------------------------------------------------------------
// Flash attention: QK^T 2-term (Kl dropped), P.V 3-term, exp2-domain softmax
// (scale folded into Q), fixed shift, term-major mma, 2 CTAs/SM.
// ---------------------------------------------------------------------------
__global__ __launch_bounds__(256, 2) void attn_mma_kernel() {
    extern __shared__ char smc[];
    const uint32_t sb = smem_u32(smc);
    const int tid = threadIdx.x, wp = tid >> 5, lane = tid & 31;
    const int qt = blockIdx.x & 15, h = (blockIdx.x >> 4) & 15, b = blockIdx.x >> 8;
    const size_t base = (size_t)(b * NH + h) * SS * DK;

    const __nv_bfloat16* qh_g = g_qh + base + (size_t)qt * QROWS * DK;
    const __nv_bfloat16* ql_g = g_ql + base + (size_t)qt * QROWS * DK;
    const __nv_bfloat16* kh_g = g_kh + base;
    const __nv_bfloat16* vh_g = g_vh + base;
    const __nv_bfloat16* vl_g = g_vl + base;

    auto issue_tile = [&](int kt, int st) {
        uint32_t sbase = sb + SM_ST(st);
        #pragma unroll
        for (int i = 0; i < 6; i++) {
            int c = tid + (i << 8);
            int arr = i >> 1;
            int row = (c >> 3) & 63, seg = c & 7;
            const __nv_bfloat16* g = (arr == 0) ? kh_g : (arr == 1) ? vh_g : vl_g;
            cp16(sbase + arr * (KTILE*RS) + row * RS + seg * 16,
                 g + (size_t)(kt * KTILE + row) * DK + seg * 8);
        }
    };

    {
        #pragma unroll
        for (int i = 0; i < 8; i++) {
            int c = tid + (i << 8);
            int arr = i >> 2;
            int row = (c >> 3) & 127, seg = c & 7;
            const __nv_bfloat16* g = arr ? ql_g : qh_g;
            cp16(sb + (arr ? SM_QL : SM_QH) + row * RS + seg * 16,
                 g + (size_t)row * DK + seg * 8);
        }
        issue_tile(0, 0);
        cp_commit();
        issue_tile(1, 1);
        cp_commit();
    }

    float sacc[8][4], oacc[8][4];
    #pragma unroll
    for (int f = 0; f < 8; f++)
        #pragma unroll
        for (int c = 0; c < 4; c++) oacc[f][c] = 0.f;
    float l0 = 0.f, l1 = 0.f;

    const int t4 = lane >> 2, tp = lane & 3;
    const int r0g = qt * QROWS + wp * 16 + t4;
    const unsigned* mrow0 = g_mbits + ((size_t)b * SS + r0g) * (SS / 32);
    const unsigned* mrow1 = mrow0 + 8 * (SS / 32);

    #pragma unroll 2
    for (int kt = 0; kt < 32; kt++) {
        int st = kt & 1;
        cp_wait1();
        __syncthreads();
        uint32_t KHb = sb + SM_ST(st);
        uint32_t VHb = KHb + KTILE*RS, VLb = KHb + 2*KTILE*RS;

        // ---- S = Q K^T (2-term) ----
        #pragma unroll
        for (int f = 0; f < 8; f++)
            #pragma unroll
            for (int c = 0; c < 4; c++) sacc[f][c] = 0.f;
        #pragma unroll
        for (int ks = 0; ks < 4; ks++) {
            uint32_t qh[4], ql[4];
            uint32_t qoff = (uint32_t)(wp * 16 + (lane & 15)) * RS + ks * 32 + (lane >> 4) * 16;
            ldsm4(qh, sb + SM_QH + qoff);
            ldsm4(ql, sb + SM_QL + qoff);
            uint32_t khf[4][4];
            #pragma unroll
            for (int p = 0; p < 4; p++) {
                uint32_t koff = (uint32_t)(p * 16 + (lane & 7) + ((lane & 16) ? 8 : 0)) * RS
                              + ks * 32 + ((lane >> 3) & 1) * 16;
                ldsm4(khf[p], KHb + koff);
            }
            #pragma unroll
            for (int p = 0; p < 4; p++)
                #pragma unroll
                for (int q2 = 0; q2 < 2; q2++)
                    mma16816(sacc[p * 2 + q2], qh, khf[p] + q2 * 2);
            #pragma unroll
            for (int p = 0; p < 4; p++)
                #pragma unroll
                for (int q2 = 0; q2 < 2; q2++)
                    mma16816(sacc[p * 2 + q2], ql, khf[p] + q2 * 2);
        }

        // ---- mask -> EPS(log2 domain), p = exp2(s), local l accumulate ----
        unsigned wa0 = __ldg(mrow0 + kt * 2), wb0 = __ldg(mrow0 + kt * 2 + 1);
        unsigned wa1 = __ldg(mrow1 + kt * 2), wb1 = __ldg(mrow1 + kt * 2 + 1);
        #pragma unroll
        for (int f = 0; f < 8; f++) {
            int sh = ((f & 3) << 3) + (tp << 1);
            unsigned u0 = ((f < 4) ? wa0 : wb0) >> sh;
            unsigned u1 = ((f < 4) ? wa1 : wb1) >> sh;
            if (!(u0 & 1)) sacc[f][0] = EPS_L2;
            if (!(u0 & 2)) sacc[f][1] = EPS_L2;
            if (!(u1 & 1)) sacc[f][2] = EPS_L2;
            if (!(u1 & 2)) sacc[f][3] = EPS_L2;
            sacc[f][0] = fexp2(sacc[f][0]);
            sacc[f][1] = fexp2(sacc[f][1]);
            sacc[f][2] = fexp2(sacc[f][2]);
            sacc[f][3] = fexp2(sacc[f][3]);
            l0 += sacc[f][0] + sacc[f][1];
            l1 += sacc[f][2] + sacc[f][3];
        }

        // ---- O += P V (3-term, term-major) ----
        #pragma unroll
        for (int ks = 0; ks < 4; ks++) {
            uint32_t ph[4], pl[4];
            const float* pa = sacc[2 * ks];
            const float* pb = sacc[2 * ks + 1];
            split2t(pa[0], pa[1], ph[0], pl[0]);      // lo retained -> trunc ok
            split2t(pa[2], pa[3], ph[1], pl[1]);
            split2t(pb[0], pb[1], ph[2], pl[2]);
            split2t(pb[2], pb[3], ph[3], pl[3]);
            uint32_t vhf[4][4], vlf[4][4];
            #pragma unroll
            for (int p = 0; p < 4; p++) {
                uint32_t voff = (uint32_t)(ks * 16 + (lane & 15)) * RS
                              + p * 32 + (lane >> 4) * 16;
                ldsm4t(vhf[p], VHb + voff);
                ldsm4t(vlf[p], VLb + voff);
            }
            #pragma unroll
            for (int p = 0; p < 4; p++)
                #pragma unroll
                for (int q2 = 0; q2 < 2; q2++)
                    mma16816(oacc[p * 2 + q2], ph, vhf[p] + q2 * 2);
            #pragma unroll
            for (int p = 0; p < 4; p++)
                #pragma unroll
                for (int q2 = 0; q2 < 2; q2++)
                    mma16816(oacc[p * 2 + q2], ph, vlf[p] + q2 * 2);
            #pragma unroll
            for (int p = 0; p < 4; p++)
                #pragma unroll
                for (int q2 = 0; q2 < 2; q2++)
                    mma16816(oacc[p * 2 + q2], pl, vhf[p] + q2 * 2);
        }

        __syncthreads();
        if (kt + 2 < 32) issue_tile(kt + 2, st);
        cp_commit();
    }

    l0 += __shfl_xor_sync(0xffffffffu, l0, 1);
    l0 += __shfl_xor_sync(0xffffffffu, l0, 2);
    l1 += __shfl_xor_sync(0xffffffffu, l1, 1);
    l1 += __shfl_xor_sync(0xffffffffu, l1, 2);

    float i0 = 1.0f / l0, i1 = 1.0f / l1;
    float* dst0 = g_attn + ((size_t)b * SS + r0g) * DM + h * 64;
    float* dst1 = dst0 + 8 * DM;
    #pragma unroll
    for (int f = 0; f < 8; f++) {
        int c = f * 8 + tp * 2;
        *(float2*)(dst0 + c) = make_float2(oacc[f][0] * i0, oacc[f][1] * i0);
        *(float2*)(dst1 + c) = make_float2(oacc[f][2] * i1, oacc[f][3] * i1);
    }
}

// ---------------------------------------------------------------------------
__global__ __launch_bounds__(256) void ln_kernel(
    const float* __restrict__ gamma, const float* __restrict__ beta,
    float* __restrict__ out)
{
    int row = blockIdx.x;
    const float* x = g_y + (size_t)row * DM;
    float v[4];
    float sum = 0.f, sq = 0.f;
    #pragma unroll
    for (int i = 0; i < 4; i++) {
        v[i] = x[threadIdx.x + (i << 8)];
        sum += v[i]; sq += v[i] * v[i];
    }
    #pragma unroll
    for (int off = 16; off; off >>= 1) {
        sum += __shfl_xor_sync(0xffffffffu, sum, off);
        sq  += __shfl_xor_sync(0xffffffffu, sq, off);
    }
    __shared__ float s1[8], s2[8];
    int w = threadIdx.x >> 5;
    if ((threadIdx.x & 31) == 0) { s1[w] = sum; s2[w] = sq; }
    __syncthreads();
    if (threadIdx.x < 32) {
        float a  = (threadIdx.x < 8) ? s1[threadIdx.x] : 0.f;
        float bq = (threadIdx.x < 8) ? s2[threadIdx.x] : 0.f;
        #pragma unroll
        for (int off = 4; off; off >>= 1) {
            a  += __shfl_xor_sync(0xffffffffu, a, off);
            bq += __shfl_xor_sync(0xffffffffu, bq, off);
        }
        if (threadIdx.x == 0) { s1[0] = a; s2[0] = bq; }
    }
    __syncthreads();
    float mean = s1[0] * (1.0f / DM);
    float var  = fmaxf((s2[0] - (float)DM * mean * mean) * (1.0f / (DM - 1)), 0.f);
    float inv  = 1.0f / (sqrtf(var) + 1e-6f);
    #pragma unroll
    for (int i = 0; i < 4; i++) {
        int c = threadIdx.x + (i << 8);
        out[(size_t)row * DM + c] = gamma[c] * (v[i] - mean) * inv + beta[c];
    }
}

// ---------------------------------------------------------------------------
extern "C" void kernel_launch(void* const* d_in, const int* in_sizes, int n_in,
                              void* d_out, int out_size) {
    const float* xq    = (const float*)d_in[0];
    const float* xk    = (const float*)d_in[1];
    const float* xv    = (const float*)d_in[2];
    const int*   mask  = (const int*)  d_in[3];
    const float* wq    = (const float*)d_in[4];
    const float* wk    = (const float*)d_in[5];
    const float* wv    = (const float*)d_in[6];
    const float* w0    = (const float*)d_in[7];
    const float* gamma = (const float*)d_in[8];
    const float* beta  = (const float*)d_in[9];
    float* out = (float*)d_out;

    pack_mask_kernel<<<(BB * SS * SS) / 256, 256>>>(mask);

    dim3 pw(DM / 64, DM / 64, 4);
    prep_w_kernel<<<pw, 256>>>(wq, wk, wv, w0);

    cudaFuncSetAttribute(gemm_mma_kernel, cudaFuncAttributeMaxDynamicSharedMemorySize, GEMM_SMEM);
    dim3 gproj(DM / NT, MTOT / MT, 3);
    gemm_mma_kernel<<<gproj, 256, GEMM_SMEM>>>(xq, xk, xv, -1, nullptr);

    cudaFuncSetAttribute(attn_mma_kernel, cudaFuncAttributeMaxDynamicSharedMemorySize, ATTN_SMEM);
    attn_mma_kernel<<<BB * NH * (SS / QROWS), 256, ATTN_SMEM>>>();

    dim3 gout(DM / NT, MTOT / MT, 1);
    gemm_mma_kernel<<<gout, 256, GEMM_SMEM>>>(nullptr, nullptr, nullptr, 3, xq);
    ln_kernel<<<MTOT, 256>>>(gamma, beta, out);
}

// round 17
// speedup vs baseline: 1.3499x; 1.2030x over previous
#include <cuda_runtime.h>
#include <cuda_bf16.h>
#include <cuda_fp16.h>
#include <stdint.h>

#define BB 4
#define SS 2048
#define DM 1024
#define NH 16
#define DK 64
#define MTOT (BB*SS)   // 8192

// GEMM tiling (mma.sync path, bf16x3 -- unchanged)
#define MT 128
#define NT 128
#define KT 32
#define NSLAB (DM/KT)          // 32
#define ROW_STRIDE 80
#define A_BYTES (MT*ROW_STRIDE)
#define STG_BYTES (4*A_BYTES)
#define GEMM_SMEM (2*STG_BYTES)

// Attention tiling -- fp16 single-term path.
// KV stage: K | V fp16, 64 rows x 128B each. 3-stage pipeline.
#define QROWS 128
#define KTILE 64
#define RS 144
#define SM_Q 0
#define KV_STG (2*KTILE*RS)                 // 18432
#define SM_ST(st) (QROWS*RS + (st)*KV_STG)
#define NSTAGE 3
#define ATTN_SMEM (QROWS*RS + NSTAGE*KV_STG)  // 73728

// Q prescale folds 1/sqrt(64) AND log2(e): scores arrive in exp2 domain.
#define QSCALE 0.18033688011112042f
// EPS mask value in the log2 domain: 1e-6 * log2(e)
#define EPS_L2 1.4426950e-6f
// fp16-range shift: p~ = 2^(s-6); cancels exactly in O/l.
#define PSHIFT 6

// ---------------------------------------------------------------------------
__device__ float g_attn[MTOT*DM];
__device__ float g_y[MTOT*DM];
__device__ unsigned g_mbits[BB*SS*SS/32];
__device__ __nv_bfloat16 g_wt_hi[4][DM*DM];
__device__ __nv_bfloat16 g_wt_lo[4][DM*DM];
__device__ __half g_q16[BB*NH*SS*DK];
__device__ __half g_k16[BB*NH*SS*DK];
__device__ __half g_v16[BB*NH*SS*DK];

// ---------------------------------------------------------------------------
__device__ __forceinline__ uint32_t smem_u32(const void* p) {
    uint32_t a;
    asm("{ .reg .u64 t; cvta.to.shared.u64 t, %1; cvt.u32.u64 %0, t; }"
        : "=r"(a) : "l"(p));
    return a;
}
__device__ __forceinline__ void ldsm4(uint32_t* r, uint32_t addr) {
    asm volatile("ldmatrix.sync.aligned.m8n8.x4.shared.b16 {%0,%1,%2,%3}, [%4];"
                 : "=r"(r[0]), "=r"(r[1]), "=r"(r[2]), "=r"(r[3]) : "r"(addr));
}
__device__ __forceinline__ void ldsm4t(uint32_t* r, uint32_t addr) {
    asm volatile("ldmatrix.sync.aligned.m8n8.x4.trans.shared.b16 {%0,%1,%2,%3}, [%4];"
                 : "=r"(r[0]), "=r"(r[1]), "=r"(r[2]), "=r"(r[3]) : "r"(addr));
}
// bf16 mma (gemm path)
__device__ __forceinline__ void mma16816(float* d, const uint32_t* a, const uint32_t* b) {
    asm volatile(
        "mma.sync.aligned.m16n8k16.row.col.f32.bf16.bf16.f32 "
        "{%0,%1,%2,%3}, {%4,%5,%6,%7}, {%8,%9}, {%0,%1,%2,%3};"
        : "+f"(d[0]), "+f"(d[1]), "+f"(d[2]), "+f"(d[3])
        : "r"(a[0]), "r"(a[1]), "r"(a[2]), "r"(a[3]), "r"(b[0]), "r"(b[1]));
}
// fp16 mma (attention path)
__device__ __forceinline__ void mma16816h(float* d, const uint32_t* a, const uint32_t* b) {
    asm volatile(
        "mma.sync.aligned.m16n8k16.row.col.f32.f16.f16.f32 "
        "{%0,%1,%2,%3}, {%4,%5,%6,%7}, {%8,%9}, {%0,%1,%2,%3};"
        : "+f"(d[0]), "+f"(d[1]), "+f"(d[2]), "+f"(d[3])
        : "r"(a[0]), "r"(a[1]), "r"(a[2]), "r"(a[3]), "r"(b[0]), "r"(b[1]));
}
__device__ __forceinline__ void cp16(uint32_t saddr, const void* gptr) {
    asm volatile("cp.async.cg.shared.global [%0], [%1], 16;"
                 :: "r"(saddr), "l"(gptr) : "memory");
}
__device__ __forceinline__ void cp_commit() { asm volatile("cp.async.commit_group;" ::: "memory"); }
__device__ __forceinline__ void cp_wait0() { asm volatile("cp.async.wait_group 0;" ::: "memory"); }
__device__ __forceinline__ void cp_wait1() { asm volatile("cp.async.wait_group 1;" ::: "memory"); }

// Truncation split (exact hi+lo; gemm A mainloop)
__device__ __forceinline__ void split2t(float x, float y, uint32_t& hi, uint32_t& lo) {
    uint32_t bx = __float_as_uint(x), by = __float_as_uint(y);
    hi = __byte_perm(bx, by, 0x7632);
    float hx = __uint_as_float(bx & 0xffff0000u);
    float hy = __uint_as_float(by & 0xffff0000u);
    __nv_bfloat162 l = __floats2bfloat162_rn(x - hx, y - hy);
    lo = *reinterpret_cast<uint32_t*>(&l);
}

// 2^(y - PSHIFT) on the FMA pipe, degree-4. Inputs |y| < ~25.
__device__ __forceinline__ float fexp2s(float y) {
    float t = y + 12582912.f;
    int   ni = __float_as_int(t) - 0x4B400000;
    float f = y - (t - 12582912.f);
    float p =            9.6181291057e-3f;
    p = fmaf(p, f, 5.5504108664e-2f);
    p = fmaf(p, f, 2.4022650696e-1f);
    p = fmaf(p, f, 6.9314718056e-1f);
    p = fmaf(p, f, 1.0f);
    return __int_as_float(__float_as_int(p) + ((ni - PSHIFT) << 23));
}

// ---------------------------------------------------------------------------
__global__ void pack_mask_kernel(const int* __restrict__ mask) {
    int i = blockIdx.x * blockDim.x + threadIdx.x;
    unsigned pred = (mask[i] != 0) ? 1u : 0u;
    unsigned w = __ballot_sync(0xffffffffu, pred);
    if ((threadIdx.x & 31) == 0) g_mbits[i >> 5] = w;
}

// ---------------------------------------------------------------------------
__global__ __launch_bounds__(256) void prep_w_kernel(
    const float* __restrict__ W0, const float* __restrict__ W1,
    const float* __restrict__ W2, const float* __restrict__ W3)
{
    __shared__ float ts[64][65];
    int widx = blockIdx.z;
    const float* W = (widx == 0) ? W0 : (widx == 1) ? W1 : (widx == 2) ? W2 : W3;
    int k0 = blockIdx.x * 64, n0 = blockIdx.y * 64;
    int tid = threadIdx.x;
    #pragma unroll
    for (int i = 0; i < 16; i++) {
        int idx = tid + (i << 8);
        int r = idx >> 6, c = idx & 63;
        ts[c][r] = W[(size_t)(k0 + r) * DM + n0 + c];
    }
    __syncthreads();
    __nv_bfloat16* Hi = g_wt_hi[widx];
    __nv_bfloat16* Lo = g_wt_lo[widx];
    #pragma unroll
    for (int i = 0; i < 16; i++) {
        int idx = tid + (i << 8);
        int r = idx >> 6, c = idx & 63;
        float v = ts[r][c];
        __nv_bfloat16 h = __float2bfloat16_rn(v);
        __nv_bfloat16 l = __float2bfloat16_rn(v - __bfloat162float(h));
        size_t o = (size_t)(n0 + r) * DM + k0 + c;
        Hi[o] = h; Lo[o] = l;
    }
}

// ---------------------------------------------------------------------------
// bf16x3 GEMM (mma.sync). Fused projections (gridDim.z==3) write fp16
// Q(prescaled)/K/V; mode 3: g_y = g_attn @ W0 + resid.
// ---------------------------------------------------------------------------
__global__ __launch_bounds__(256, 2) void gemm_mma_kernel(
    const float* __restrict__ A0, const float* __restrict__ A1,
    const float* __restrict__ A2, int mode_in, const float* __restrict__ resid)
{
    extern __shared__ char smc[];
    const uint32_t sb = smem_u32(smc);
    const int tid = threadIdx.x, wid = tid >> 5, lane = tid & 31;
    const int bm = blockIdx.y * MT, bn = blockIdx.x * NT;
    const int warp_m = wid >> 2, warp_n = wid & 3;
    const int mode = (mode_in == 3) ? 3 : (int)blockIdx.z;
    const int widx = mode;
    const float* __restrict__ A =
        (mode == 3) ? (const float*)g_attn : (mode == 0) ? A0 : (mode == 1) ? A1 : A2;
    const __nv_bfloat16* __restrict__ BHi = g_wt_hi[widx];
    const __nv_bfloat16* __restrict__ BLo = g_wt_lo[widx];

    float acc[4][4][4];
    #pragma unroll
    for (int i = 0; i < 4; i++)
        #pragma unroll
        for (int j = 0; j < 4; j++)
            #pragma unroll
            for (int c = 0; c < 4; c++) acc[i][j][c] = 0.f;

    const int arow_ld = tid >> 1, acol_ld = (tid & 1) * 16;
    const int a_r = (lane & 15), a_c8 = (lane >> 4) * 8;
    const int b_n = (lane & 7) + ((lane & 16) ? 8 : 0);
    const int b_k8 = ((lane >> 3) & 1) * 8;

    auto issueB = [&](int s, int stage) {
        int k0 = s * KT;
        uint32_t bh = sb + stage * STG_BYTES + 2 * A_BYTES;
        uint32_t bl = bh + A_BYTES;
        #pragma unroll
        for (int i = 0; i < 2; i++) {
            int c = tid + (i << 8);
            int row = c >> 2, seg = c & 3;
            size_t go = (size_t)(bn + row) * DM + k0 + seg * 8;
            uint32_t so = (uint32_t)row * ROW_STRIDE + seg * 16;
            cp16(bh + so, BHi + go);
            cp16(bl + so, BLo + go);
        }
        cp_commit();
    };
    auto ldgA = [&](int s, float* af) {
        const float4* src = (const float4*)(A + (size_t)(bm + arow_ld) * DM + s * KT + acol_ld);
        #pragma unroll
        for (int q = 0; q < 4; q++) ((float4*)af)[q] = src[q];
    };
    auto stsA = [&](int stage, const float* af) {
        uint32_t ah = sb + stage * STG_BYTES;
        uint32_t al = ah + A_BYTES;
        uint32_t ro = (uint32_t)arow_ld * ROW_STRIDE + acol_ld * 2;
        #pragma unroll
        for (int q = 0; q < 4; q++) {
            uint32_t hv0, lv0, hv1, lv1;
            split2t(af[4*q], af[4*q+1], hv0, lv0);
            split2t(af[4*q+2], af[4*q+3], hv1, lv1);
            uint32_t so = ro + q * 8;
            asm volatile("st.shared.v2.b32 [%0], {%1,%2};" :: "r"(ah + so), "r"(hv0), "r"(hv1) : "memory");
            asm volatile("st.shared.v2.b32 [%0], {%1,%2};" :: "r"(al + so), "r"(lv0), "r"(lv1) : "memory");
        }
    };
    auto compute_half = [&](int stage, int ks) {
        uint32_t ah_b = sb + stage * STG_BYTES;
        uint32_t al_b = ah_b + A_BYTES;
        uint32_t bh_b = ah_b + 2 * A_BYTES;
        uint32_t bl_b = ah_b + 3 * A_BYTES;
        uint32_t bh[8], bl[8];
        #pragma unroll
        for (int p = 0; p < 2; p++) {
            uint32_t bo = (uint32_t)(warp_n * 32 + p * 16 + b_n) * ROW_STRIDE
                        + (ks * 16 + b_k8) * 2;
            ldsm4(bh + 4 * p, bh_b + bo);
            ldsm4(bl + 4 * p, bl_b + bo);
        }
        #pragma unroll
        for (int fi = 0; fi < 4; fi++) {
            uint32_t ao = (uint32_t)(warp_m * 64 + fi * 16 + a_r) * ROW_STRIDE
                        + (ks * 16 + a_c8) * 2;
            uint32_t ahf[4], alf[4];
            ldsm4(ahf, ah_b + ao);
            ldsm4(alf, al_b + ao);
            #pragma unroll
            for (int fj = 0; fj < 4; fj++)
                mma16816(acc[fi][fj], ahf, bh + (fj >> 1) * 4 + (fj & 1) * 2);
            #pragma unroll
            for (int fj = 0; fj < 4; fj++)
                mma16816(acc[fi][fj], ahf, bl + (fj >> 1) * 4 + (fj & 1) * 2);
            #pragma unroll
            for (int fj = 0; fj < 4; fj++)
                mma16816(acc[fi][fj], alf, bh + (fj >> 1) * 4 + (fj & 1) * 2);
        }
    };

    {
        float af[16];
        issueB(0, 0);
        ldgA(0, af);
        stsA(0, af);
        cp_wait0();
        __syncthreads();
    }
    for (int s = 0; s < NSLAB; s++) {
        int stage = s & 1;
        float af[16];
        bool pf = (s + 1 < NSLAB);
        if (pf) { issueB(s + 1, stage ^ 1); ldgA(s + 1, af); }
        compute_half(stage, 0);
        if (pf) stsA(stage ^ 1, af);
        compute_half(stage, 1);
        if (pf) cp_wait0();
        __syncthreads();
    }

    const int t4 = lane >> 2, tp = (lane & 3) * 2;
    #pragma unroll
    for (int fi = 0; fi < 4; fi++) {
        #pragma unroll
        for (int h2 = 0; h2 < 2; h2++) {
            int m = bm + warp_m * 64 + fi * 16 + t4 + h2 * 8;
            if (mode < 3) {
                __half* o16 = (mode == 0) ? g_q16 : (mode == 1) ? g_k16 : g_v16;
                float scale = (mode == 0) ? QSCALE : 1.0f;
                int b = m >> 11, srow = m & (SS - 1);
                #pragma unroll
                for (int fj = 0; fj < 4; fj++) {
                    int n = bn + warp_n * 32 + fj * 8 + tp;
                    int h = n >> 6, d = n & 63;
                    __half2 hv = __floats2half2_rn(acc[fi][fj][h2*2] * scale,
                                                   acc[fi][fj][h2*2+1] * scale);
                    size_t o = ((((size_t)b * NH + h) * SS) + srow) * DK + d;
                    *(__half2*)(o16 + o) = hv;
                }
            } else {
                #pragma unroll
                for (int fj = 0; fj < 4; fj++) {
                    int n = bn + warp_n * 32 + fj * 8 + tp;
                    size_t o = (size_t)m * DM + n;
                    float2 rv = *(const float2*)(resid + o);
                    *(float2*)(g_y + o) = make_float2(acc[fi][fj][h2*2] + rv.x,
                                                      acc[fi][fj][h2*2+1] + rv.y);
                }
            }
        }
    }
}

// ---------------------------------------------------------------------------
// Flash attention: fp16 single-term QK^T and P.V, exp2-domain softmax with
// folded 2^-6 shift (cancels in O/l), fixed shift, 3-stage cp.async pipeline
// with ONE barrier per kt, 2 CTAs/SM.
// ---------------------------------------------------------------------------
__global__ __launch_bounds__(256, 2) void attn_mma_kernel() {
    extern __shared__ char smc[];
    const uint32_t sb = smem_u32(smc);
    const int tid = threadIdx.x, wp = tid >> 5, lane = tid & 31;
    const int qt = blockIdx.x & 15, h = (blockIdx.x >> 4) & 15, b = blockIdx.x >> 8;
    const size_t base = (size_t)(b * NH + h) * SS * DK;

    const __half* q_g = g_q16 + base + (size_t)qt * QROWS * DK;
    const __half* k_g = g_k16 + base;
    const __half* v_g = g_v16 + base;

    // KV stage: K | V, 64 rows x 128B each -> 4 cp16 per thread
    auto issue_tile = [&](int kt, int st) {
        uint32_t sbase = sb + SM_ST(st);
        #pragma unroll
        for (int i = 0; i < 4; i++) {
            int c = tid + (i << 8);
            int arr = i >> 1;                 // 0:K 1:V  (c>>9 == i>>1)
            int row = (c >> 3) & 63, seg = c & 7;
            const __half* g = arr ? v_g : k_g;
            cp16(sbase + arr * (KTILE*RS) + row * RS + seg * 16,
                 g + (size_t)(kt * KTILE + row) * DK + seg * 8);
        }
    };

    {
        #pragma unroll
        for (int i = 0; i < 4; i++) {
            int c = tid + (i << 8);
            int row = c >> 3, seg = c & 7;     // row 0..127
            cp16(sb + SM_Q + row * RS + seg * 16, q_g + (size_t)row * DK + seg * 8);
        }
        issue_tile(0, 0);
        cp_commit();
        issue_tile(1, 1);
        cp_commit();
    }

    float sacc[8][4], oacc[8][4];
    #pragma unroll
    for (int f = 0; f < 8; f++)
        #pragma unroll
        for (int c = 0; c < 4; c++) oacc[f][c] = 0.f;
    float l0 = 0.f, l1 = 0.f;

    const int t4 = lane >> 2, tp = lane & 3;
    const int r0g = qt * QROWS + wp * 16 + t4;
    const unsigned* mrow0 = g_mbits + ((size_t)b * SS + r0g) * (SS / 32);
    const unsigned* mrow1 = mrow0 + 8 * (SS / 32);

    int st = 0, st2 = 2;     // st = kt % 3, st2 = (kt+2) % 3
    #pragma unroll 1
    for (int kt = 0; kt < 32; kt++) {
        cp_wait1();
        __syncthreads();      // tile kt ready; all warps done reading tile kt-1
        if (kt + 2 < 32) { issue_tile(kt + 2, st2); cp_commit(); }
        uint32_t KB = sb + SM_ST(st);
        uint32_t VB = KB + KTILE*RS;

        // ---- S = Q K^T (fp16, 1 term) ----
        #pragma unroll
        for (int f = 0; f < 8; f++)
            #pragma unroll
            for (int c = 0; c < 4; c++) sacc[f][c] = 0.f;
        #pragma unroll
        for (int ks = 0; ks < 4; ks++) {
            uint32_t qf[4];
            uint32_t qoff = (uint32_t)(wp * 16 + (lane & 15)) * RS + ks * 32 + (lane >> 4) * 16;
            ldsm4(qf, sb + SM_Q + qoff);
            uint32_t kf[4][4];
            #pragma unroll
            for (int p = 0; p < 4; p++) {
                uint32_t koff = (uint32_t)(p * 16 + (lane & 7) + ((lane & 16) ? 8 : 0)) * RS
                              + ks * 32 + ((lane >> 3) & 1) * 16;
                ldsm4(kf[p], KB + koff);
            }
            #pragma unroll
            for (int p = 0; p < 4; p++)
                #pragma unroll
                for (int q2 = 0; q2 < 2; q2++)
                    mma16816h(sacc[p * 2 + q2], qf, kf[p] + q2 * 2);
        }

        // ---- mask -> EPS(log2), p~ = 2^(s-6), local l accumulate ----
        unsigned wa0 = __ldg(mrow0 + kt * 2), wb0 = __ldg(mrow0 + kt * 2 + 1);
        unsigned wa1 = __ldg(mrow1 + kt * 2), wb1 = __ldg(mrow1 + kt * 2 + 1);
        #pragma unroll
        for (int f = 0; f < 8; f++) {
            int sh = ((f & 3) << 3) + (tp << 1);
            unsigned u0 = ((f < 4) ? wa0 : wb0) >> sh;
            unsigned u1 = ((f < 4) ? wa1 : wb1) >> sh;
            if (!(u0 & 1)) sacc[f][0] = EPS_L2;
            if (!(u0 & 2)) sacc[f][1] = EPS_L2;
            if (!(u1 & 1)) sacc[f][2] = EPS_L2;
            if (!(u1 & 2)) sacc[f][3] = EPS_L2;
            sacc[f][0] = fexp2s(sacc[f][0]);
            sacc[f][1] = fexp2s(sacc[f][1]);
            sacc[f][2] = fexp2s(sacc[f][2]);
            sacc[f][3] = fexp2s(sacc[f][3]);
            l0 += sacc[f][0] + sacc[f][1];
            l1 += sacc[f][2] + sacc[f][3];
        }

        // ---- O += P V (fp16, 1 term) ----
        #pragma unroll
        for (int ks = 0; ks < 4; ks++) {
            uint32_t ph[4];
            const float* pa = sacc[2 * ks];
            const float* pb = sacc[2 * ks + 1];
            __half2 h0 = __floats2half2_rn(pa[0], pa[1]);
            __half2 h1 = __floats2half2_rn(pa[2], pa[3]);
            __half2 h2 = __floats2half2_rn(pb[0], pb[1]);
            __half2 h3 = __floats2half2_rn(pb[2], pb[3]);
            ph[0] = *reinterpret_cast<uint32_t*>(&h0);
            ph[1] = *reinterpret_cast<uint32_t*>(&h1);
            ph[2] = *reinterpret_cast<uint32_t*>(&h2);
            ph[3] = *reinterpret_cast<uint32_t*>(&h3);
            uint32_t vf[4][4];
            #pragma unroll
            for (int p = 0; p < 4; p++) {
                uint32_t voff = (uint32_t)(ks * 16 + (lane & 15)) * RS
                              + p * 32 + (lane >> 4) * 16;
                ldsm4t(vf[p], VB + voff);
            }
            #pragma unroll
            for (int p = 0; p < 4; p++)
                #pragma unroll
                for (int q2 = 0; q2 < 2; q2++)
                    mma16816h(oacc[p * 2 + q2], ph, vf[p] + q2 * 2);
        }

        st = (st == 2) ? 0 : st + 1;
        st2 = (st2 == 2) ? 0 : st2 + 1;
    }

    l0 += __shfl_xor_sync(0xffffffffu, l0, 1);
    l0 += __shfl_xor_sync(0xffffffffu, l0, 2);
    l1 += __shfl_xor_sync(0xffffffffu, l1, 1);
    l1 += __shfl_xor_sync(0xffffffffu, l1, 2);

    float i0 = 1.0f / l0, i1 = 1.0f / l1;
    float* dst0 = g_attn + ((size_t)b * SS + r0g) * DM + h * 64;
    float* dst1 = dst0 + 8 * DM;
    #pragma unroll
    for (int f = 0; f < 8; f++) {
        int c = f * 8 + tp * 2;
        *(float2*)(dst0 + c) = make_float2(oacc[f][0] * i0, oacc[f][1] * i0);
        *(float2*)(dst1 + c) = make_float2(oacc[f][2] * i1, oacc[f][3] * i1);
    }
}

// ---------------------------------------------------------------------------
__global__ __launch_bounds__(256) void ln_kernel(
    const float* __restrict__ gamma, const float* __restrict__ beta,
    float* __restrict__ out)
{
    int row = blockIdx.x;
    const float* x = g_y + (size_t)row * DM;
    float v[4];
    float sum = 0.f, sq = 0.f;
    #pragma unroll
    for (int i = 0; i < 4; i++) {
        v[i] = x[threadIdx.x + (i << 8)];
        sum += v[i]; sq += v[i] * v[i];
    }
    #pragma unroll
    for (int off = 16; off; off >>= 1) {
        sum += __shfl_xor_sync(0xffffffffu, sum, off);
        sq  += __shfl_xor_sync(0xffffffffu, sq, off);
    }
    __shared__ float s1[8], s2[8];
    int w = threadIdx.x >> 5;
    if ((threadIdx.x & 31) == 0) { s1[w] = sum; s2[w] = sq; }
    __syncthreads();
    if (threadIdx.x < 32) {
        float a  = (threadIdx.x < 8) ? s1[threadIdx.x] : 0.f;
        float bq = (threadIdx.x < 8) ? s2[threadIdx.x] : 0.f;
        #pragma unroll
        for (int off = 4; off; off >>= 1) {
            a  += __shfl_xor_sync(0xffffffffu, a, off);
            bq += __shfl_xor_sync(0xffffffffu, bq, off);
        }
        if (threadIdx.x == 0) { s1[0] = a; s2[0] = bq; }
    }
    __syncthreads();
    float mean = s1[0] * (1.0f / DM);
    float var  = fmaxf((s2[0] - (float)DM * mean * mean) * (1.0f / (DM - 1)), 0.f);
    float inv  = 1.0f / (sqrtf(var) + 1e-6f);
    #pragma unroll
    for (int i = 0; i < 4; i++) {
        int c = threadIdx.x + (i << 8);
        out[(size_t)row * DM + c] = gamma[c] * (v[i] - mean) * inv + beta[c];
    }
}

// ---------------------------------------------------------------------------
extern "C" void kernel_launch(void* const* d_in, const int* in_sizes, int n_in,
                              void* d_out, int out_size) {
    const float* xq    = (const float*)d_in[0];
    const float* xk    = (const float*)d_in[1];
    const float* xv    = (const float*)d_in[2];
    const int*   mask  = (const int*)  d_in[3];
    const float* wq    = (const float*)d_in[4];
    const float* wk    = (const float*)d_in[5];
    const float* wv    = (const float*)d_in[6];
    const float* w0    = (const float*)d_in[7];
    const float* gamma = (const float*)d_in[8];
    const float* beta  = (const float*)d_in[9];
    float* out = (float*)d_out;

    pack_mask_kernel<<<(BB * SS * SS) / 256, 256>>>(mask);

    dim3 pw(DM / 64, DM / 64, 4);
    prep_w_kernel<<<pw, 256>>>(wq, wk, wv, w0);

    cudaFuncSetAttribute(gemm_mma_kernel, cudaFuncAttributeMaxDynamicSharedMemorySize, GEMM_SMEM);
    dim3 gproj(DM / NT, MTOT / MT, 3);
    gemm_mma_kernel<<<gproj, 256, GEMM_SMEM>>>(xq, xk, xv, -1, nullptr);

    cudaFuncSetAttribute(attn_mma_kernel, cudaFuncAttributeMaxDynamicSharedMemorySize, ATTN_SMEM);
    attn_mma_kernel<<<BB * NH * (SS / QROWS), 256, ATTN_SMEM>>>();

    dim3 gout(DM / NT, MTOT / MT, 1);
    gemm_mma_kernel<<<gout, 256, GEMM_SMEM>>>(nullptr, nullptr, nullptr, 3, xq);
    ln_kernel<<<MTOT, 256>>>(gamma, beta, out);
}